// round 10
// baseline (speedup 1.0000x reference)
#include <cuda_runtime.h>
#include <cuda_bf16.h>
#include <cstdint>
#include <math.h>

#define BATCH 32
#define CIN   128
#define HWN   4096
#define EB    128
#define EE    384
#define GUARD 512
#define NX    ((size_t)BATCH * CIN * HWN)

// SMEM layout (bytes): A rows=[k][tok] 272B, W rows=[n][k] 144B
#define AROW  272
#define WROW  144
#define OFF_AH   0
#define OFF_AL   17408
#define OFF_WH   34816
#define OFF_WL   53248
#define OFF_ATTN 71680
#define SMEM_SZ  73728

// ---------------- device scratch (no allocation allowed) ----------------
__device__ float    g_fused[(size_t)BATCH * EE * HWN];          // [b][c][hw]
__device__ __align__(16) uint16_t g_xh[4][NX + 2 * GUARD];      // hi planes, shift 0..3
__device__ __align__(16) uint16_t g_xl[4][NX + 2 * GUARD];      // lo planes, shift 0..3
__device__ uint16_t g_w3h[9  * 128 * 128], g_w3l[9  * 128 * 128];  // [tap][o][ci]
__device__ uint16_t g_w5h[25 * 128 * 128], g_w5l[25 * 128 * 128];
__device__ uint16_t g_w7h[49 * 128 * 128], g_w7l[49 * 128 * 128];
__device__ uint16_t g_wfh[EE * EE],        g_wfl[EE * EE];         // [o][c]
__device__ float    g_avg[BATCH * EE];
__device__ float    g_max[BATCH * EE];
__device__ float    g_attn[BATCH * EE];

// ---------------- helpers -------------------------------------------------
__device__ __forceinline__ uint32_t smem_u32(const void* p) {
    uint32_t a;
    asm("{ .reg .u64 t; cvta.to.shared.u64 t, %1; cvt.u32.u64 %0, t; }" : "=r"(a) : "l"(p));
    return a;
}

#define LDSM_X4(r0, r1, r2, r3, addr) \
    asm volatile("ldmatrix.sync.aligned.m8n8.x4.shared.b16 {%0,%1,%2,%3}, [%4];" \
                 : "=r"(r0), "=r"(r1), "=r"(r2), "=r"(r3) : "r"(addr))

#define LDSM_X4T(r0, r1, r2, r3, addr) \
    asm volatile("ldmatrix.sync.aligned.m8n8.x4.trans.shared.b16 {%0,%1,%2,%3}, [%4];" \
                 : "=r"(r0), "=r"(r1), "=r"(r2), "=r"(r3) : "r"(addr))

__device__ __forceinline__ void mma_bf16(float* c, const uint32_t* a,
                                         uint32_t b0, uint32_t b1) {
    asm volatile(
        "mma.sync.aligned.m16n8k16.row.col.f32.bf16.bf16.f32 "
        "{%0,%1,%2,%3}, {%4,%5,%6,%7}, {%8,%9}, {%0,%1,%2,%3};"
        : "+f"(c[0]), "+f"(c[1]), "+f"(c[2]), "+f"(c[3])
        : "r"(a[0]), "r"(a[1]), "r"(a[2]), "r"(a[3]), "r"(b0), "r"(b1));
}

__device__ __forceinline__ void bf_split(float v, uint16_t& h, uint16_t& l) {
    __nv_bfloat16 bh = __float2bfloat16(v);
    float rem = v - __bfloat162float(bh);
    __nv_bfloat16 bl = __float2bfloat16(rem);
    h = *reinterpret_cast<uint16_t*>(&bh);
    l = *reinterpret_cast<uint16_t*>(&bl);
}

// ---------------- prep kernels --------------------------------------------
__global__ void prep_x(const float* __restrict__ x) {
    size_t i = (size_t)blockIdx.x * blockDim.x + threadIdx.x;
    if (i >= NX) return;
    uint16_t h, l;
    bf_split(x[i], h, l);
    #pragma unroll
    for (int s = 0; s < 4; ++s) {
        g_xh[s][GUARD + i - s] = h;   // plane_s[j] = x[j+s]
        g_xl[s][GUARD + i - s] = l;
    }
}

template<int TAPS>
__global__ void prep_wc(const float* __restrict__ w) {
    uint16_t* wh = (TAPS == 3) ? g_w3h : (TAPS == 5) ? g_w5h : g_w7h;
    uint16_t* wl = (TAPS == 3) ? g_w3l : (TAPS == 5) ? g_w5l : g_w7l;
    int idx = blockIdx.x * blockDim.x + threadIdx.x;
    if (idx >= TAPS * TAPS * 128 * 128) return;
    int tap  = idx >> 14;
    int rest = idx & 16383;
    int o    = rest >> 7;
    int ci   = rest & 127;
    float v = w[(o * CIN + ci) * (TAPS * TAPS) + tap];
    uint16_t h, l; bf_split(v, h, l);
    wh[idx] = h;
    wl[idx] = l;
}

__global__ void prep_wf(const float* __restrict__ fw) {
    int idx = blockIdx.x * blockDim.x + threadIdx.x;
    if (idx >= EE * EE) return;
    uint16_t h, l; bf_split(fw[idx], h, l);
    g_wfh[idx] = h;
    g_wfl[idx] = l;
}

// ---------------- tensor-core matmul kernel (mma.sync bf16, 3-term split) --
// TAPS in {3,5,7}: conv branch -> g_fused at channel offset c0.
// TAPS==0: 1x1 fusion GEMM with attention gate -> out[b][tok][e].
// CTA: 128 tokens x 128 out-channels; 4 warps (2M x 2N), warp tile 64x64.
// A SMEM: [k][tok] rows 272B via ldmatrix.trans. W SMEM: [n][k] rows 144B.
template<int TAPS>
__global__ __launch_bounds__(128, 2) void mm_kernel(const float* __restrict__ bias,
                                                    float* __restrict__ out, int c0) {
    extern __shared__ char smem[];
    uint16_t* Ah = (uint16_t*)(smem + OFF_AH);
    uint16_t* Al = (uint16_t*)(smem + OFF_AL);
    uint16_t* Wh = (uint16_t*)(smem + OFF_WH);
    uint16_t* Wl = (uint16_t*)(smem + OFF_WL);
    float* s_attn = (float*)(smem + OFF_ATTN);

    const int tid = threadIdx.x;
    const int b   = blockIdx.y;
    const int tileTok = blockIdx.x * 128;
    const int nb = (TAPS == 0) ? blockIdx.z : 0;

    if (TAPS == 0)
        for (int i = tid; i < EE; i += 128) s_attn[i] = g_attn[b * EE + i];

    const int lane = tid & 31, wid = tid >> 5;
    const int wm = wid & 1, wn = wid >> 1;

    float acc[4][8][4];
    #pragma unroll
    for (int mi = 0; mi < 4; ++mi)
        #pragma unroll
        for (int ni = 0; ni < 8; ++ni)
            #pragma unroll
            for (int q = 0; q < 4; ++q) acc[mi][ni][q] = 0.f;

    const uint32_t sAh = smem_u32(Ah), sAl = smem_u32(Al);
    const uint32_t sWh = smem_u32(Wh), sWl = smem_u32(Wl);

    const int NT  = (TAPS == 0) ? 1 : TAPS * TAPS;
    const int NCC = (TAPS == 0) ? 6 : 2;   // 64-wide K chunks per tap
    const uint16_t* gwh = (TAPS == 3) ? g_w3h : (TAPS == 5) ? g_w5h
                         : (TAPS == 7) ? g_w7h : g_wfh;
    const uint16_t* gwl = (TAPS == 3) ? g_w3l : (TAPS == 5) ? g_w5l
                         : (TAPS == 7) ? g_w7l : g_wfl;

    // ldmatrix addresses
    // A (trans, rows=k): lanes 0-7 k0-7/m0, 8-15 k0-7/m8, 16-23 k8-15/m0, 24-31 k8-15/m8
    const uint32_t aRow0 = (lane & 7) + ((lane >> 4) << 3);
    const uint32_t aCol0 = wm * 64 + ((lane >> 3) & 1) * 8;
    // W (non-trans, rows=n)
    const uint32_t wRow0 = wn * 64 + (lane & 7) + ((lane >> 4) << 3);
    const uint32_t wKoff = ((lane >> 3) & 1) << 3;

    // staging maps (128 threads)
    const int rA  = tid >> 5;       // A: k-row base (stride 4)
    const int cA4 = tid & 31;       // A: uint2 col -> tokens 4*cA4..+3
    const int pyB = tileTok >> 6;

    for (int tap = 0; tap < NT; ++tap) {
        uint32_t m0 = 0xFFFFFFFFu, m1 = 0xFFFFFFFFu;
        const uint16_t *ph = nullptr, *pl = nullptr;
        long long Bv = 0;
        if (TAPS > 0) {
            int dy = tap / TAPS - TAPS / 2, dx = tap % TAPS - TAPS / 2;
            int B  = tileTok + dy * 64 + dx;
            int s  = B & 3;
            Bv = B - s;
            ph = g_xh[s] + GUARD;
            pl = g_xl[s] + GUARD;
            bool rv0 = (unsigned)(pyB + dy) < 64u;
            bool rv1 = (unsigned)(pyB + 1 + dy) < 64u;
            int lo = dx > 0 ? 0 : -dx;
            int hi = dx > 0 ? 64 - dx : 64;
            int t0 = cA4 * 4;                 // first of 4 tokens (same image row)
            bool rv = (t0 >> 6) ? rv1 : rv0;
            int j0 = t0 & 63;
            bool v0 = rv && (j0     >= lo) && (j0     < hi);
            bool v1 = rv && (j0 + 1 >= lo) && (j0 + 1 < hi);
            bool v2 = rv && (j0 + 2 >= lo) && (j0 + 2 < hi);
            bool v3 = rv && (j0 + 3 >= lo) && (j0 + 3 < hi);
            m0 = (v0 ? 0xFFFFu : 0u) | (v1 ? 0xFFFF0000u : 0u);
            m1 = (v2 ? 0xFFFFu : 0u) | (v3 ? 0xFFFF0000u : 0u);
        }

        for (int cc = 0; cc < NCC; ++cc) {
            __syncthreads();   // previous chunk's compute done

            // ---- stage A: [64 k][128 tok], hi/lo planes ----
            if (TAPS > 0) {
                long long base = (long long)(b * CIN + cc * 64 + rA) * HWN + Bv;
                #pragma unroll
                for (int it = 0; it < 16; ++it) {
                    uint2 uh = __ldg((const uint2*)((const uint32_t*)(ph + base)) + cA4);
                    uint2 ul = __ldg((const uint2*)((const uint32_t*)(pl + base)) + cA4);
                    uh.x &= m0; uh.y &= m1;
                    ul.x &= m0; ul.y &= m1;
                    int r = rA + it * 4;
                    *(uint2*)((char*)Ah + r * AROW + cA4 * 8) = uh;
                    *(uint2*)((char*)Al + r * AROW + cA4 * 8) = ul;
                    base += 4LL * HWN;
                }
            } else {
                const int cb = cc * 64;
                #pragma unroll
                for (int it = 0; it < 16; ++it) {
                    int r = rA + it * 4;
                    float4 v = __ldg((const float4*)(g_fused +
                                    ((size_t)b * EE + cb + r) * HWN + tileTok) + cA4);
                    float a = s_attn[cb + r];
                    uint16_t h0, l0, h1, l1, h2, l2, h3, l3;
                    bf_split(v.x * a, h0, l0);
                    bf_split(v.y * a, h1, l1);
                    bf_split(v.z * a, h2, l2);
                    bf_split(v.w * a, h3, l3);
                    uint2 hh = make_uint2((uint32_t)h0 | ((uint32_t)h1 << 16),
                                          (uint32_t)h2 | ((uint32_t)h3 << 16));
                    uint2 ll = make_uint2((uint32_t)l0 | ((uint32_t)l1 << 16),
                                          (uint32_t)l2 | ((uint32_t)l3 << 16));
                    *(uint2*)((char*)Ah + r * AROW + cA4 * 8) = hh;
                    *(uint2*)((char*)Al + r * AROW + cA4 * 8) = ll;
                }
            }

            // ---- stage W: [128 n][64 k], one row per thread, uint4 ----
            {
                size_t roff = (TAPS == 0)
                    ? ((size_t)(nb * 128 + tid) * EE + cc * 64)
                    : ((size_t)(tap * 128 + tid) * 128 + cc * 64);
                #pragma unroll
                for (int jj = 0; jj < 8; ++jj) {
                    uint4 vh = __ldg((const uint4*)(gwh + roff + jj * 8));
                    uint4 vl = __ldg((const uint4*)(gwl + roff + jj * 8));
                    *(uint4*)((char*)Wh + tid * WROW + jj * 16) = vh;
                    *(uint4*)((char*)Wl + tid * WROW + jj * 16) = vl;
                }
            }
            __syncthreads();

            // ---- compute: 4 k16 steps, 3-term bf16 split ----
            #pragma unroll
            for (int k16 = 0; k16 < 4; ++k16) {
                const uint32_t kb = k16 * 16;
                uint32_t ahf[4][4], alf[4][4];
                #pragma unroll
                for (int mi = 0; mi < 4; ++mi) {
                    uint32_t ao = (kb + aRow0) * AROW + (aCol0 + mi * 16) * 2;
                    LDSM_X4T(ahf[mi][0], ahf[mi][1], ahf[mi][2], ahf[mi][3], sAh + ao);
                    LDSM_X4T(alf[mi][0], alf[mi][1], alf[mi][2], alf[mi][3], sAl + ao);
                }
                #pragma unroll
                for (int nh = 0; nh < 4; ++nh) {
                    uint32_t wo = (wRow0 + nh * 16) * WROW + (kb + wKoff) * 2;
                    uint32_t whf[4], wlf[4];
                    LDSM_X4(whf[0], whf[1], whf[2], whf[3], sWh + wo);
                    LDSM_X4(wlf[0], wlf[1], wlf[2], wlf[3], sWl + wo);
                    #pragma unroll
                    for (int mi = 0; mi < 4; ++mi) {
                        mma_bf16(acc[mi][nh * 2],     ahf[mi], whf[0], whf[1]);
                        mma_bf16(acc[mi][nh * 2 + 1], ahf[mi], whf[2], whf[3]);
                        mma_bf16(acc[mi][nh * 2],     alf[mi], whf[0], whf[1]);
                        mma_bf16(acc[mi][nh * 2 + 1], alf[mi], whf[2], whf[3]);
                        mma_bf16(acc[mi][nh * 2],     ahf[mi], wlf[0], wlf[1]);
                        mma_bf16(acc[mi][nh * 2 + 1], ahf[mi], wlf[2], wlf[3]);
                    }
                }
            }
        }
    }

    // ---- epilogue ----
    const int r0 = wm * 64 + (lane >> 2);
    if (TAPS > 0) {
        #pragma unroll
        for (int ni = 0; ni < 8; ++ni) {
            int ch = wn * 64 + ni * 8 + (lane & 3) * 2;
            float bv0 = __ldg(bias + ch), bv1 = __ldg(bias + ch + 1);
            float* d0 = g_fused + ((size_t)b * EE + c0 + ch) * HWN + tileTok;
            float* d1 = d0 + HWN;
            #pragma unroll
            for (int mi = 0; mi < 4; ++mi) {
                int m = r0 + mi * 16;
                d0[m]     = acc[mi][ni][0] + bv0;
                d1[m]     = acc[mi][ni][1] + bv1;
                d0[m + 8] = acc[mi][ni][2] + bv0;
                d1[m + 8] = acc[mi][ni][3] + bv1;
            }
        }
    } else {
        #pragma unroll
        for (int ni = 0; ni < 8; ++ni) {
            int chl = wn * 64 + ni * 8 + (lane & 3) * 2;
            int e = nb * 128 + chl;
            float bv0 = __ldg(bias + e), bv1 = __ldg(bias + e + 1);
            #pragma unroll
            for (int mi = 0; mi < 4; ++mi) {
                int m = r0 + mi * 16;
                float* da = out + ((size_t)b * HWN + tileTok + m) * EE + e;
                float* db = out + ((size_t)b * HWN + tileTok + m + 8) * EE + e;
                *(float2*)da = make_float2(acc[mi][ni][0] + bv0, acc[mi][ni][1] + bv1);
                *(float2*)db = make_float2(acc[mi][ni][2] + bv0, acc[mi][ni][3] + bv1);
            }
        }
    }
}

// ---------------- pool / attention / layernorm (unchanged, passing) ------
__global__ void pool_kernel() {
    int row = blockIdx.x;
    const float* p = g_fused + (size_t)row * HWN;
    int tid = threadIdx.x;
    float s = 0.f, m = -INFINITY;
    for (int i = tid; i < HWN; i += 256) { float v = p[i]; s += v; m = fmaxf(m, v); }
    __shared__ float ss[256], sm[256];
    ss[tid] = s; sm[tid] = m;
    __syncthreads();
    for (int st = 128; st > 0; st >>= 1) {
        if (tid < st) { ss[tid] += ss[tid + st]; sm[tid] = fmaxf(sm[tid], sm[tid + st]); }
        __syncthreads();
    }
    if (tid == 0) { g_avg[row] = ss[0] * (1.f / HWN); g_max[row] = sm[0]; }
}

__global__ void attn_kernel(const float* __restrict__ cw1, const float* __restrict__ cw2) {
    __shared__ float h1[24], h2[24];
    int b = blockIdx.x;
    int tid = threadIdx.x;
    if (tid < 24) {
        float s = 0.f;
        const float* w = cw1 + tid * EE;
        const float* v = g_avg + b * EE;
        #pragma unroll 4
        for (int c = 0; c < EE; ++c) s += v[c] * w[c];
        h1[tid] = fmaxf(s, 0.f);
    } else if (tid < 48) {
        int j = tid - 24;
        float s = 0.f;
        const float* w = cw1 + j * EE;
        const float* v = g_max + b * EE;
        #pragma unroll 4
        for (int c = 0; c < EE; ++c) s += v[c] * w[c];
        h2[j] = fmaxf(s, 0.f);
    }
    __syncthreads();
    float s = 0.f;
    const float* w = cw2 + tid * 24;
    #pragma unroll
    for (int j = 0; j < 24; ++j) s += (h1[j] + h2[j]) * w[j];
    g_attn[b * EE + tid] = 1.f / (1.f + expf(-s));
}

__global__ void ln_kernel(float* __restrict__ out, const float* __restrict__ g,
                          const float* __restrict__ beta) {
    int tokrow = blockIdx.x;
    float* p = out + (size_t)tokrow * EE;
    int tid = threadIdx.x;
    float v0 = p[tid], v1 = p[tid + 128], v2 = p[tid + 256];
    float s = v0 + v1 + v2;
    float q = v0 * v0 + v1 * v1 + v2 * v2;
    #pragma unroll
    for (int off = 16; off > 0; off >>= 1) {
        s += __shfl_down_sync(0xffffffffu, s, off);
        q += __shfl_down_sync(0xffffffffu, q, off);
    }
    __shared__ float rs[4], rq[4];
    __shared__ float smean, srstd;
    int wid = tid >> 5, lane = tid & 31;
    if (lane == 0) { rs[wid] = s; rq[wid] = q; }
    __syncthreads();
    if (tid == 0) {
        float ts = rs[0] + rs[1] + rs[2] + rs[3];
        float tq = rq[0] + rq[1] + rq[2] + rq[3];
        float mean = ts * (1.f / EE);
        float var  = tq * (1.f / EE) - mean * mean;
        smean = mean;
        srstd = rsqrtf(var + 1e-5f);
    }
    __syncthreads();
    float mean = smean, rstd = srstd;
    p[tid]       = (v0 - mean) * rstd * g[tid]       + beta[tid];
    p[tid + 128] = (v1 - mean) * rstd * g[tid + 128] + beta[tid + 128];
    p[tid + 256] = (v2 - mean) * rstd * g[tid + 256] + beta[tid + 256];
}

// ---------------- launch ---------------------------------------------------
extern "C" void kernel_launch(void* const* d_in, const int* in_sizes, int n_in,
                              void* d_out, int out_size) {
    const float* x   = (const float*)d_in[0];
    const float* w3  = (const float*)d_in[1];
    const float* b3  = (const float*)d_in[2];
    const float* w5  = (const float*)d_in[3];
    const float* b5  = (const float*)d_in[4];
    const float* w7  = (const float*)d_in[5];
    const float* b7  = (const float*)d_in[6];
    const float* cw1 = (const float*)d_in[7];
    const float* cw2 = (const float*)d_in[8];
    const float* fw  = (const float*)d_in[9];
    const float* fb  = (const float*)d_in[10];
    const float* lng = (const float*)d_in[11];
    const float* lnb = (const float*)d_in[12];
    float* out = (float*)d_out;

    cudaFuncSetAttribute(mm_kernel<3>, cudaFuncAttributeMaxDynamicSharedMemorySize, SMEM_SZ);
    cudaFuncSetAttribute(mm_kernel<5>, cudaFuncAttributeMaxDynamicSharedMemorySize, SMEM_SZ);
    cudaFuncSetAttribute(mm_kernel<7>, cudaFuncAttributeMaxDynamicSharedMemorySize, SMEM_SZ);
    cudaFuncSetAttribute(mm_kernel<0>, cudaFuncAttributeMaxDynamicSharedMemorySize, SMEM_SZ);

    prep_x<<<(int)((NX + 255) / 256), 256>>>(x);
    prep_wc<3><<<(9  * 16384 + 255) / 256, 256>>>(w3);
    prep_wc<5><<<(25 * 16384 + 255) / 256, 256>>>(w5);
    prep_wc<7><<<(49 * 16384 + 255) / 256, 256>>>(w7);
    prep_wf<<<(EE * EE + 255) / 256, 256>>>(fw);

    dim3 cgrid(HWN / 128, BATCH);
    mm_kernel<3><<<cgrid, 128, SMEM_SZ>>>(b3, nullptr, 0);
    mm_kernel<5><<<cgrid, 128, SMEM_SZ>>>(b5, nullptr, EB);
    mm_kernel<7><<<cgrid, 128, SMEM_SZ>>>(b7, nullptr, 2 * EB);

    pool_kernel<<<BATCH * EE, 256>>>();
    attn_kernel<<<BATCH, EE>>>(cw1, cw2);

    dim3 ggrid(HWN / 128, BATCH, 3);
    mm_kernel<0><<<ggrid, 128, SMEM_SZ>>>(fb, out, 0);

    ln_kernel<<<BATCH * HWN, 128>>>(out, lng, lnb);
}

// round 11
// speedup vs baseline: 1.1846x; 1.1846x over previous
#include <cuda_runtime.h>
#include <cuda_bf16.h>
#include <cstdint>
#include <math.h>

#define BATCH 32
#define CIN   128
#define HWN   4096
#define EB    128
#define EE    384
#define PROW  72
#define PIMG  5184      // 72*72 padded image (4-border)
#define NPL   ((size_t)BATCH * CIN * PIMG)

// SMEM layout (bytes): A rows=[k][tok] 272B, W rows=[n][k] 144B
#define AROW  272
#define WROW  144
#define OFF_AH   0
#define OFF_AL   17408
#define OFF_WH   34816
#define OFF_WL   53248
#define OFF_ATTN 71680
#define SMEM_SZ  73728

// ---------------- device scratch (no allocation allowed) ----------------
__device__ float    g_fused[(size_t)BATCH * EE * HWN];   // [b][c][hw]
__device__ __align__(16) uint16_t g_ph[4][NPL];          // hi planes, shift 0..3, zero-padded
__device__ __align__(16) uint16_t g_pl[4][NPL];          // lo planes
__device__ uint16_t g_w3h[9  * 128 * 128], g_w3l[9  * 128 * 128];  // [tap][o][ci]
__device__ uint16_t g_w5h[25 * 128 * 128], g_w5l[25 * 128 * 128];
__device__ uint16_t g_w7h[49 * 128 * 128], g_w7l[49 * 128 * 128];
__device__ uint16_t g_wfh[EE * EE],        g_wfl[EE * EE];         // [o][c]
__device__ float    g_avg[BATCH * EE];
__device__ float    g_max[BATCH * EE];
__device__ float    g_attn[BATCH * EE];

// ---------------- helpers -------------------------------------------------
__device__ __forceinline__ uint32_t smem_u32(const void* p) {
    uint32_t a;
    asm("{ .reg .u64 t; cvta.to.shared.u64 t, %1; cvt.u32.u64 %0, t; }" : "=r"(a) : "l"(p));
    return a;
}

#define LDSM_X4(r0, r1, r2, r3, addr) \
    asm volatile("ldmatrix.sync.aligned.m8n8.x4.shared.b16 {%0,%1,%2,%3}, [%4];" \
                 : "=r"(r0), "=r"(r1), "=r"(r2), "=r"(r3) : "r"(addr))

#define LDSM_X4T(r0, r1, r2, r3, addr) \
    asm volatile("ldmatrix.sync.aligned.m8n8.x4.trans.shared.b16 {%0,%1,%2,%3}, [%4];" \
                 : "=r"(r0), "=r"(r1), "=r"(r2), "=r"(r3) : "r"(addr))

__device__ __forceinline__ void cp8(uint32_t dst, const void* src) {
    asm volatile("cp.async.ca.shared.global [%0], [%1], 8;" :: "r"(dst), "l"(src));
}
__device__ __forceinline__ void cp16(uint32_t dst, const void* src) {
    asm volatile("cp.async.cg.shared.global [%0], [%1], 16;" :: "r"(dst), "l"(src));
}
#define CP_COMMIT() asm volatile("cp.async.commit_group;" ::: "memory")
#define CP_WAIT0()  asm volatile("cp.async.wait_group 0;" ::: "memory")

__device__ __forceinline__ void mma_bf16(float* c, const uint32_t* a,
                                         uint32_t b0, uint32_t b1) {
    asm volatile(
        "mma.sync.aligned.m16n8k16.row.col.f32.bf16.bf16.f32 "
        "{%0,%1,%2,%3}, {%4,%5,%6,%7}, {%8,%9}, {%0,%1,%2,%3};"
        : "+f"(c[0]), "+f"(c[1]), "+f"(c[2]), "+f"(c[3])
        : "r"(a[0]), "r"(a[1]), "r"(a[2]), "r"(a[3]), "r"(b0), "r"(b1));
}

__device__ __forceinline__ void bf_split(float v, uint16_t& h, uint16_t& l) {
    __nv_bfloat16 bh = __float2bfloat16(v);
    float rem = v - __bfloat162float(bh);
    __nv_bfloat16 bl = __float2bfloat16(rem);
    h = *reinterpret_cast<uint16_t*>(&bh);
    l = *reinterpret_cast<uint16_t*>(&bl);
}

// ---------------- prep kernels --------------------------------------------
// Padded shifted planes: g_ph[s][bc][r][j] = hi(x[bc][r-4][j-4+s]), zero outside.
__global__ void prep_x(const float* __restrict__ x) {
    size_t idx = (size_t)blockIdx.x * blockDim.x + threadIdx.x;
    if (idx >= 4ull * NPL) return;
    int    s   = (int)(idx / NPL);
    size_t rem = idx % NPL;
    size_t bc  = rem / PIMG;
    int    p   = (int)(rem % PIMG);
    int r = p / PROW, j = p % PROW;
    int oy = r - 4, ox = j - 4 + s;
    float v = 0.f;
    if ((unsigned)oy < 64u && (unsigned)ox < 64u)
        v = x[bc * HWN + oy * 64 + ox];
    uint16_t h, l; bf_split(v, h, l);
    g_ph[s][rem] = h;
    g_pl[s][rem] = l;
}

template<int TAPS>
__global__ void prep_wc(const float* __restrict__ w) {
    uint16_t* wh = (TAPS == 3) ? g_w3h : (TAPS == 5) ? g_w5h : g_w7h;
    uint16_t* wl = (TAPS == 3) ? g_w3l : (TAPS == 5) ? g_w5l : g_w7l;
    int idx = blockIdx.x * blockDim.x + threadIdx.x;
    if (idx >= TAPS * TAPS * 128 * 128) return;
    int tap  = idx >> 14;
    int rest = idx & 16383;
    int o    = rest >> 7;
    int ci   = rest & 127;
    float v = w[(o * CIN + ci) * (TAPS * TAPS) + tap];
    uint16_t h, l; bf_split(v, h, l);
    wh[idx] = h;
    wl[idx] = l;
}

__global__ void prep_wf(const float* __restrict__ fw) {
    int idx = blockIdx.x * blockDim.x + threadIdx.x;
    if (idx >= EE * EE) return;
    uint16_t h, l; bf_split(fw[idx], h, l);
    g_wfh[idx] = h;
    g_wfl[idx] = l;
}

// ---------------- tensor-core matmul kernel (mma.sync bf16, 3-term split) --
// R9 compute config: CTA 128x128, 8 warps (4M x 2N), warp tile 32x64, K chunks 64.
// Staging via cp.async from zero-padded shifted planes (no masks).
template<int TAPS>
__global__ __launch_bounds__(256, 2) void mm_kernel(const float* __restrict__ bias,
                                                    float* __restrict__ out, int c0) {
    extern __shared__ char smem[];
    uint16_t* Ah = (uint16_t*)(smem + OFF_AH);
    uint16_t* Al = (uint16_t*)(smem + OFF_AL);
    float* s_attn = (float*)(smem + OFF_ATTN);

    const int tid = threadIdx.x;
    const int b   = blockIdx.y;
    const int tileTok = blockIdx.x * 128;
    const int nb = (TAPS == 0) ? blockIdx.z : 0;

    if (TAPS == 0)
        for (int i = tid; i < EE; i += 256) s_attn[i] = g_attn[b * EE + i];

    const int lane = tid & 31, wid = tid >> 5;
    const int wm = wid & 3, wn = wid >> 2;
    const int oL = tid & 127, hf = tid >> 7;

    float acc[2][8][4];
    #pragma unroll
    for (int mi = 0; mi < 2; ++mi)
        #pragma unroll
        for (int ni = 0; ni < 8; ++ni)
            #pragma unroll
            for (int q = 0; q < 4; ++q) acc[mi][ni][q] = 0.f;

    const uint32_t sAh = smem_u32(smem + OFF_AH), sAl = smem_u32(smem + OFF_AL);
    const uint32_t sWh = smem_u32(smem + OFF_WH), sWl = smem_u32(smem + OFF_WL);

    const int NT  = (TAPS == 0) ? 1 : TAPS * TAPS;
    const int NCC = (TAPS == 0) ? 6 : 2;   // 64-wide K chunks per tap
    const uint16_t* gwh = (TAPS == 3) ? g_w3h : (TAPS == 5) ? g_w5h
                         : (TAPS == 7) ? g_w7h : g_wfh;
    const uint16_t* gwl = (TAPS == 3) ? g_w3l : (TAPS == 5) ? g_w5l
                         : (TAPS == 7) ? g_w7l : g_wfl;

    // ldmatrix addresses (R9-proven maps)
    const uint32_t aRow0 = (lane & 7) + ((lane >> 4) << 3);
    const uint32_t aCol0 = wm * 32 + ((lane >> 3) & 1) * 8;
    const uint32_t wRow0 = wn * 64 + (lane & 7) + ((lane >> 4) << 3);
    const uint32_t wKoff = ((lane >> 3) & 1) << 3;

    // staging maps (256 threads)
    const int wrp = tid >> 5;        // A: k-row base (stride 8) / warp id
    const int c8  = tid & 31;        // A: 8B col -> tokens 4*c8..+3
    const int pyB = tileTok >> 6;

    for (int tap = 0; tap < NT; ++tap) {
        const uint16_t *ph = nullptr, *pl = nullptr;
        size_t rjBase = 0;
        if (TAPS > 0) {
            int dy = tap / TAPS - TAPS / 2, dx = tap % TAPS - TAPS / 2;
            int s  = dx & 3;
            int d4 = dx - s;                         // -4 or 0
            int trow = c8 >> 4;                      // 0/1 within 128-token tile
            int px0  = (4 * c8) & 63;
            int r = pyB + trow + dy + 4;             // padded row, in [1,70]
            int j = px0 + 4 + d4;                    // padded col, mult of 4
            rjBase = (size_t)r * PROW + j;
            ph = g_ph[s];
            pl = g_pl[s];
        }

        for (int cc = 0; cc < NCC; ++cc) {
            __syncthreads();   // previous chunk's compute done

            // ---- stage A: [64 k][128 tok] via cp.async 8B (conv) ----
            if (TAPS > 0) {
                size_t bcbase = (size_t)(b * CIN + cc * 64 + wrp) * PIMG + rjBase;
                uint32_t dh = sAh + wrp * AROW + c8 * 8;
                uint32_t dl = sAl + wrp * AROW + c8 * 8;
                #pragma unroll
                for (int it = 0; it < 8; ++it) {
                    cp8(dh, ph + bcbase);
                    cp8(dl, pl + bcbase);
                    bcbase += 8ull * PIMG;
                    dh += 8 * AROW;
                    dl += 8 * AROW;
                }
            }

            // ---- stage W: [128 n][64 k] via cp.async 16B ----
            {
                size_t roff = (TAPS == 0)
                    ? ((size_t)(nb * 128 + oL) * EE + cc * 64 + hf * 32)
                    : ((size_t)(tap * 128 + oL) * 128 + cc * 64 + hf * 32);
                uint32_t dwh = sWh + oL * WROW + hf * 64;
                uint32_t dwl = sWl + oL * WROW + hf * 64;
                #pragma unroll
                for (int jj = 0; jj < 4; ++jj) {
                    cp16(dwh + jj * 16, gwh + roff + jj * 8);
                    cp16(dwl + jj * 16, gwl + roff + jj * 8);
                }
            }

            // ---- stage A (fusion): attention gate + bf_split in regs ----
            if (TAPS == 0) {
                const int cb = cc * 64;
                #pragma unroll
                for (int it = 0; it < 8; ++it) {
                    int r = wrp + it * 8;
                    float4 v = __ldg((const float4*)(g_fused +
                                    ((size_t)b * EE + cb + r) * HWN + tileTok) + c8);
                    float a = s_attn[cb + r];
                    uint16_t h0, l0, h1, l1, h2, l2, h3, l3;
                    bf_split(v.x * a, h0, l0);
                    bf_split(v.y * a, h1, l1);
                    bf_split(v.z * a, h2, l2);
                    bf_split(v.w * a, h3, l3);
                    uint2 hh = make_uint2((uint32_t)h0 | ((uint32_t)h1 << 16),
                                          (uint32_t)h2 | ((uint32_t)h3 << 16));
                    uint2 ll = make_uint2((uint32_t)l0 | ((uint32_t)l1 << 16),
                                          (uint32_t)l2 | ((uint32_t)l3 << 16));
                    *(uint2*)((char*)Ah + r * AROW + c8 * 8) = hh;
                    *(uint2*)((char*)Al + r * AROW + c8 * 8) = ll;
                }
            }

            CP_COMMIT();
            CP_WAIT0();
            __syncthreads();

            // ---- compute: 4 k16 steps, 3-term bf16 split ----
            #pragma unroll
            for (int k16 = 0; k16 < 4; ++k16) {
                const uint32_t kb = k16 * 16;
                uint32_t ahf[2][4], alf[2][4];
                #pragma unroll
                for (int mi = 0; mi < 2; ++mi) {
                    uint32_t ao = (kb + aRow0) * AROW + (aCol0 + mi * 16) * 2;
                    LDSM_X4T(ahf[mi][0], ahf[mi][1], ahf[mi][2], ahf[mi][3], sAh + ao);
                    LDSM_X4T(alf[mi][0], alf[mi][1], alf[mi][2], alf[mi][3], sAl + ao);
                }
                #pragma unroll
                for (int nh = 0; nh < 4; ++nh) {
                    uint32_t wo = (wRow0 + nh * 16) * WROW + (kb + wKoff) * 2;
                    uint32_t whf[4], wlf[4];
                    LDSM_X4(whf[0], whf[1], whf[2], whf[3], sWh + wo);
                    LDSM_X4(wlf[0], wlf[1], wlf[2], wlf[3], sWl + wo);
                    #pragma unroll
                    for (int mi = 0; mi < 2; ++mi) {
                        mma_bf16(acc[mi][nh * 2],     ahf[mi], whf[0], whf[1]);
                        mma_bf16(acc[mi][nh * 2 + 1], ahf[mi], whf[2], whf[3]);
                        mma_bf16(acc[mi][nh * 2],     alf[mi], whf[0], whf[1]);
                        mma_bf16(acc[mi][nh * 2 + 1], alf[mi], whf[2], whf[3]);
                        mma_bf16(acc[mi][nh * 2],     ahf[mi], wlf[0], wlf[1]);
                        mma_bf16(acc[mi][nh * 2 + 1], ahf[mi], wlf[2], wlf[3]);
                    }
                }
            }
        }
    }

    // ---- epilogue (R9-proven) ----
    const int r0 = wm * 32 + (lane >> 2);
    if (TAPS > 0) {
        #pragma unroll
        for (int ni = 0; ni < 8; ++ni) {
            int ch = wn * 64 + ni * 8 + (lane & 3) * 2;
            float bv0 = __ldg(bias + ch), bv1 = __ldg(bias + ch + 1);
            float* d0 = g_fused + ((size_t)b * EE + c0 + ch) * HWN + tileTok;
            float* d1 = d0 + HWN;
            #pragma unroll
            for (int mi = 0; mi < 2; ++mi) {
                int m = r0 + mi * 16;
                d0[m]     = acc[mi][ni][0] + bv0;
                d1[m]     = acc[mi][ni][1] + bv1;
                d0[m + 8] = acc[mi][ni][2] + bv0;
                d1[m + 8] = acc[mi][ni][3] + bv1;
            }
        }
    } else {
        #pragma unroll
        for (int ni = 0; ni < 8; ++ni) {
            int chl = wn * 64 + ni * 8 + (lane & 3) * 2;
            int e = nb * 128 + chl;
            float bv0 = __ldg(bias + e), bv1 = __ldg(bias + e + 1);
            #pragma unroll
            for (int mi = 0; mi < 2; ++mi) {
                int m = r0 + mi * 16;
                float* da = out + ((size_t)b * HWN + tileTok + m) * EE + e;
                float* db = out + ((size_t)b * HWN + tileTok + m + 8) * EE + e;
                *(float2*)da = make_float2(acc[mi][ni][0] + bv0, acc[mi][ni][1] + bv1);
                *(float2*)db = make_float2(acc[mi][ni][2] + bv0, acc[mi][ni][3] + bv1);
            }
        }
    }
}

// ---------------- pool / attention / layernorm (unchanged, passing) ------
__global__ void pool_kernel() {
    int row = blockIdx.x;
    const float* p = g_fused + (size_t)row * HWN;
    int tid = threadIdx.x;
    float s = 0.f, m = -INFINITY;
    for (int i = tid; i < HWN; i += 256) { float v = p[i]; s += v; m = fmaxf(m, v); }
    __shared__ float ss[256], sm[256];
    ss[tid] = s; sm[tid] = m;
    __syncthreads();
    for (int st = 128; st > 0; st >>= 1) {
        if (tid < st) { ss[tid] += ss[tid + st]; sm[tid] = fmaxf(sm[tid], sm[tid + st]); }
        __syncthreads();
    }
    if (tid == 0) { g_avg[row] = ss[0] * (1.f / HWN); g_max[row] = sm[0]; }
}

__global__ void attn_kernel(const float* __restrict__ cw1, const float* __restrict__ cw2) {
    __shared__ float h1[24], h2[24];
    int b = blockIdx.x;
    int tid = threadIdx.x;
    if (tid < 24) {
        float s = 0.f;
        const float* w = cw1 + tid * EE;
        const float* v = g_avg + b * EE;
        #pragma unroll 4
        for (int c = 0; c < EE; ++c) s += v[c] * w[c];
        h1[tid] = fmaxf(s, 0.f);
    } else if (tid < 48) {
        int j = tid - 24;
        float s = 0.f;
        const float* w = cw1 + j * EE;
        const float* v = g_max + b * EE;
        #pragma unroll 4
        for (int c = 0; c < EE; ++c) s += v[c] * w[c];
        h2[j] = fmaxf(s, 0.f);
    }
    __syncthreads();
    float s = 0.f;
    const float* w = cw2 + tid * 24;
    #pragma unroll
    for (int j = 0; j < 24; ++j) s += (h1[j] + h2[j]) * w[j];
    g_attn[b * EE + tid] = 1.f / (1.f + expf(-s));
}

__global__ void ln_kernel(float* __restrict__ out, const float* __restrict__ g,
                          const float* __restrict__ beta) {
    int tokrow = blockIdx.x;
    float* p = out + (size_t)tokrow * EE;
    int tid = threadIdx.x;
    float v0 = p[tid], v1 = p[tid + 128], v2 = p[tid + 256];
    float s = v0 + v1 + v2;
    float q = v0 * v0 + v1 * v1 + v2 * v2;
    #pragma unroll
    for (int off = 16; off > 0; off >>= 1) {
        s += __shfl_down_sync(0xffffffffu, s, off);
        q += __shfl_down_sync(0xffffffffu, q, off);
    }
    __shared__ float rs[4], rq[4];
    __shared__ float smean, srstd;
    int wid = tid >> 5, lane = tid & 31;
    if (lane == 0) { rs[wid] = s; rq[wid] = q; }
    __syncthreads();
    if (tid == 0) {
        float ts = rs[0] + rs[1] + rs[2] + rs[3];
        float tq = rq[0] + rq[1] + rq[2] + rq[3];
        float mean = ts * (1.f / EE);
        float var  = tq * (1.f / EE) - mean * mean;
        smean = mean;
        srstd = rsqrtf(var + 1e-5f);
    }
    __syncthreads();
    float mean = smean, rstd = srstd;
    p[tid]       = (v0 - mean) * rstd * g[tid]       + beta[tid];
    p[tid + 128] = (v1 - mean) * rstd * g[tid + 128] + beta[tid + 128];
    p[tid + 256] = (v2 - mean) * rstd * g[tid + 256] + beta[tid + 256];
}

// ---------------- launch ---------------------------------------------------
extern "C" void kernel_launch(void* const* d_in, const int* in_sizes, int n_in,
                              void* d_out, int out_size) {
    const float* x   = (const float*)d_in[0];
    const float* w3  = (const float*)d_in[1];
    const float* b3  = (const float*)d_in[2];
    const float* w5  = (const float*)d_in[3];
    const float* b5  = (const float*)d_in[4];
    const float* w7  = (const float*)d_in[5];
    const float* b7  = (const float*)d_in[6];
    const float* cw1 = (const float*)d_in[7];
    const float* cw2 = (const float*)d_in[8];
    const float* fw  = (const float*)d_in[9];
    const float* fb  = (const float*)d_in[10];
    const float* lng = (const float*)d_in[11];
    const float* lnb = (const float*)d_in[12];
    float* out = (float*)d_out;

    cudaFuncSetAttribute(mm_kernel<3>, cudaFuncAttributeMaxDynamicSharedMemorySize, SMEM_SZ);
    cudaFuncSetAttribute(mm_kernel<5>, cudaFuncAttributeMaxDynamicSharedMemorySize, SMEM_SZ);
    cudaFuncSetAttribute(mm_kernel<7>, cudaFuncAttributeMaxDynamicSharedMemorySize, SMEM_SZ);
    cudaFuncSetAttribute(mm_kernel<0>, cudaFuncAttributeMaxDynamicSharedMemorySize, SMEM_SZ);

    prep_x<<<(int)((4ull * NPL + 255) / 256), 256>>>(x);
    prep_wc<3><<<(9  * 16384 + 255) / 256, 256>>>(w3);
    prep_wc<5><<<(25 * 16384 + 255) / 256, 256>>>(w5);
    prep_wc<7><<<(49 * 16384 + 255) / 256, 256>>>(w7);
    prep_wf<<<(EE * EE + 255) / 256, 256>>>(fw);

    dim3 cgrid(HWN / 128, BATCH);
    mm_kernel<3><<<cgrid, 256, SMEM_SZ>>>(b3, nullptr, 0);
    mm_kernel<5><<<cgrid, 256, SMEM_SZ>>>(b5, nullptr, EB);
    mm_kernel<7><<<cgrid, 256, SMEM_SZ>>>(b7, nullptr, 2 * EB);

    pool_kernel<<<BATCH * EE, 256>>>();
    attn_kernel<<<BATCH, EE>>>(cw1, cw2);

    dim3 ggrid(HWN / 128, BATCH, 3);
    mm_kernel<0><<<ggrid, 256, SMEM_SZ>>>(fb, out, 0);

    ln_kernel<<<BATCH * HWN, 128>>>(out, lng, lnb);
}

// round 12
// speedup vs baseline: 1.6437x; 1.3876x over previous
#include <cuda_runtime.h>
#include <cuda_fp16.h>
#include <cstdint>
#include <math.h>

#define BATCH 32
#define CIN   128
#define HWN   4096
#define EB    128
#define EE    384
#define PROW  72
#define PIMG  5184      // 72*72 padded image (4-border)
#define NPL   ((size_t)BATCH * CIN * PIMG)

// SMEM layout (bytes): A rows=[k][tok] 272B, W rows=[n][k] 144B
#define AROW  272
#define WROW  144
#define OFF_AH   0
#define OFF_AL   17408
#define OFF_WH   34816
#define OFF_WL   53248
#define OFF_ATTN 71680
#define SMEM_SZ  73728

// ---------------- device scratch (no allocation allowed) ----------------
__device__ float    g_fused[(size_t)BATCH * EE * HWN];   // [b][c][hw]
__device__ __align__(16) uint16_t g_ph[4][NPL];          // fp16 hi planes, shift 0..3
__device__ __align__(16) uint16_t g_pl[4][NPL];          // fp16 lo planes
__device__ uint16_t g_w3h[9  * 128 * 128];               // [tap][o][ci], fp16 hi only
__device__ uint16_t g_w5h[25 * 128 * 128];
__device__ uint16_t g_w7h[49 * 128 * 128];
__device__ uint16_t g_wfh[EE * EE], g_wfl[EE * EE];      // fusion: hi + lo
__device__ float    g_avg[BATCH * EE];
__device__ float    g_max[BATCH * EE];
__device__ float    g_attn[BATCH * EE];

// ---------------- helpers -------------------------------------------------
__device__ __forceinline__ uint32_t smem_u32(const void* p) {
    uint32_t a;
    asm("{ .reg .u64 t; cvta.to.shared.u64 t, %1; cvt.u32.u64 %0, t; }" : "=r"(a) : "l"(p));
    return a;
}

#define LDSM_X4(r0, r1, r2, r3, addr) \
    asm volatile("ldmatrix.sync.aligned.m8n8.x4.shared.b16 {%0,%1,%2,%3}, [%4];" \
                 : "=r"(r0), "=r"(r1), "=r"(r2), "=r"(r3) : "r"(addr))

#define LDSM_X4T(r0, r1, r2, r3, addr) \
    asm volatile("ldmatrix.sync.aligned.m8n8.x4.trans.shared.b16 {%0,%1,%2,%3}, [%4];" \
                 : "=r"(r0), "=r"(r1), "=r"(r2), "=r"(r3) : "r"(addr))

__device__ __forceinline__ void cp8(uint32_t dst, const void* src) {
    asm volatile("cp.async.ca.shared.global [%0], [%1], 8;" :: "r"(dst), "l"(src));
}
__device__ __forceinline__ void cp16(uint32_t dst, const void* src) {
    asm volatile("cp.async.cg.shared.global [%0], [%1], 16;" :: "r"(dst), "l"(src));
}
#define CP_COMMIT() asm volatile("cp.async.commit_group;" ::: "memory")
#define CP_WAIT0()  asm volatile("cp.async.wait_group 0;" ::: "memory")

__device__ __forceinline__ void mma_f16(float* c, const uint32_t* a,
                                        uint32_t b0, uint32_t b1) {
    asm volatile(
        "mma.sync.aligned.m16n8k16.row.col.f32.f16.f16.f32 "
        "{%0,%1,%2,%3}, {%4,%5,%6,%7}, {%8,%9}, {%0,%1,%2,%3};"
        : "+f"(c[0]), "+f"(c[1]), "+f"(c[2]), "+f"(c[3])
        : "r"(a[0]), "r"(a[1]), "r"(a[2]), "r"(a[3]), "r"(b0), "r"(b1));
}

__device__ __forceinline__ void f16_split(float v, uint16_t& h, uint16_t& l) {
    __half hh = __float2half_rn(v);
    float rem = v - __half2float(hh);
    __half hl = __float2half_rn(rem);
    h = *reinterpret_cast<uint16_t*>(&hh);
    l = *reinterpret_cast<uint16_t*>(&hl);
}
__device__ __forceinline__ uint16_t f16_hi(float v) {
    __half hh = __float2half_rn(v);
    return *reinterpret_cast<uint16_t*>(&hh);
}

// ---------------- prep kernels --------------------------------------------
// Padded shifted planes: g_ph[s][bc][r][j] = f16hi(x[bc][r-4][j-4+s]), zero outside.
__global__ void prep_x(const float* __restrict__ x) {
    size_t idx = (size_t)blockIdx.x * blockDim.x + threadIdx.x;
    if (idx >= 4ull * NPL) return;
    int    s   = (int)(idx / NPL);
    size_t rem = idx % NPL;
    size_t bc  = rem / PIMG;
    int    p   = (int)(rem % PIMG);
    int r = p / PROW, j = p % PROW;
    int oy = r - 4, ox = j - 4 + s;
    float v = 0.f;
    if ((unsigned)oy < 64u && (unsigned)ox < 64u)
        v = x[bc * HWN + oy * 64 + ox];
    uint16_t h, l; f16_split(v, h, l);
    g_ph[s][rem] = h;
    g_pl[s][rem] = l;
}

template<int TAPS>
__global__ void prep_wc(const float* __restrict__ w) {
    uint16_t* wh = (TAPS == 3) ? g_w3h : (TAPS == 5) ? g_w5h : g_w7h;
    int idx = blockIdx.x * blockDim.x + threadIdx.x;
    if (idx >= TAPS * TAPS * 128 * 128) return;
    int tap  = idx >> 14;
    int rest = idx & 16383;
    int o    = rest >> 7;
    int ci   = rest & 127;
    wh[idx] = f16_hi(w[(o * CIN + ci) * (TAPS * TAPS) + tap]);
}

__global__ void prep_wf(const float* __restrict__ fw) {
    int idx = blockIdx.x * blockDim.x + threadIdx.x;
    if (idx >= EE * EE) return;
    uint16_t h, l; f16_split(fw[idx], h, l);
    g_wfh[idx] = h;
    g_wfl[idx] = l;
}

// ---------------- tensor-core matmul kernel (mma.sync fp16 split) ---------
// Convs (TAPS 3/5/7): 2-term split (Ah*Wh + Al*Wh).  Fusion (TAPS 0): 3-term.
// CTA 128x128, 8 warps (4M x 2N), warp tile 32x64, K chunks 64, cp.async staging.
template<int TAPS>
__global__ __launch_bounds__(256, 2) void mm_kernel(const float* __restrict__ bias,
                                                    float* __restrict__ out, int c0) {
    extern __shared__ char smem[];
    uint16_t* Ah = (uint16_t*)(smem + OFF_AH);
    uint16_t* Al = (uint16_t*)(smem + OFF_AL);
    float* s_attn = (float*)(smem + OFF_ATTN);

    const int tid = threadIdx.x;
    const int b   = blockIdx.y;
    const int tileTok = blockIdx.x * 128;
    const int nb = (TAPS == 0) ? blockIdx.z : 0;

    if (TAPS == 0)
        for (int i = tid; i < EE; i += 256) s_attn[i] = g_attn[b * EE + i];

    const int lane = tid & 31, wid = tid >> 5;
    const int wm = wid & 3, wn = wid >> 2;
    const int oL = tid & 127, hf = tid >> 7;

    float acc[2][8][4];
    #pragma unroll
    for (int mi = 0; mi < 2; ++mi)
        #pragma unroll
        for (int ni = 0; ni < 8; ++ni)
            #pragma unroll
            for (int q = 0; q < 4; ++q) acc[mi][ni][q] = 0.f;

    const uint32_t sAh = smem_u32(smem + OFF_AH), sAl = smem_u32(smem + OFF_AL);
    const uint32_t sWh = smem_u32(smem + OFF_WH), sWl = smem_u32(smem + OFF_WL);

    const int NT  = (TAPS == 0) ? 1 : TAPS * TAPS;
    const int NCC = (TAPS == 0) ? 6 : 2;   // 64-wide K chunks per tap
    const uint16_t* gwh = (TAPS == 3) ? g_w3h : (TAPS == 5) ? g_w5h
                         : (TAPS == 7) ? g_w7h : g_wfh;

    // ldmatrix addresses (proven maps)
    const uint32_t aRow0 = (lane & 7) + ((lane >> 4) << 3);
    const uint32_t aCol0 = wm * 32 + ((lane >> 3) & 1) * 8;
    const uint32_t wRow0 = wn * 64 + (lane & 7) + ((lane >> 4) << 3);
    const uint32_t wKoff = ((lane >> 3) & 1) << 3;

    // staging maps (256 threads)
    const int wrp = tid >> 5;        // A: k-row base (stride 8) / warp id
    const int c8  = tid & 31;        // A: 8B col -> tokens 4*c8..+3
    const int pyB = tileTok >> 6;

    for (int tap = 0; tap < NT; ++tap) {
        const uint16_t *ph = nullptr, *pl = nullptr;
        size_t rjBase = 0;
        if (TAPS > 0) {
            int dy = tap / TAPS - TAPS / 2, dx = tap % TAPS - TAPS / 2;
            int s  = dx & 3;
            int d4 = dx - s;                         // -4 or 0
            int trow = c8 >> 4;                      // 0/1 within 128-token tile
            int px0  = (4 * c8) & 63;
            int r = pyB + trow + dy + 4;             // padded row
            int j = px0 + 4 + d4;                    // padded col, mult of 4
            rjBase = (size_t)r * PROW + j;
            ph = g_ph[s];
            pl = g_pl[s];
        }

        for (int cc = 0; cc < NCC; ++cc) {
            __syncthreads();   // previous chunk's compute done

            // ---- stage A: [64 k][128 tok] via cp.async 8B (conv) ----
            if (TAPS > 0) {
                size_t bcbase = (size_t)(b * CIN + cc * 64 + wrp) * PIMG + rjBase;
                uint32_t dh = sAh + wrp * AROW + c8 * 8;
                uint32_t dl = sAl + wrp * AROW + c8 * 8;
                #pragma unroll
                for (int it = 0; it < 8; ++it) {
                    cp8(dh, ph + bcbase);
                    cp8(dl, pl + bcbase);
                    bcbase += 8ull * PIMG;
                    dh += 8 * AROW;
                    dl += 8 * AROW;
                }
            }

            // ---- stage W hi (and lo for fusion) via cp.async 16B ----
            {
                size_t roff = (TAPS == 0)
                    ? ((size_t)(nb * 128 + oL) * EE + cc * 64 + hf * 32)
                    : ((size_t)(tap * 128 + oL) * 128 + cc * 64 + hf * 32);
                uint32_t dwh = sWh + oL * WROW + hf * 64;
                #pragma unroll
                for (int jj = 0; jj < 4; ++jj)
                    cp16(dwh + jj * 16, gwh + roff + jj * 8);
                if (TAPS == 0) {
                    uint32_t dwl = sWl + oL * WROW + hf * 64;
                    #pragma unroll
                    for (int jj = 0; jj < 4; ++jj)
                        cp16(dwl + jj * 16, g_wfl + roff + jj * 8);
                }
            }

            // ---- stage A (fusion): attention gate + f16_split in regs ----
            if (TAPS == 0) {
                const int cb = cc * 64;
                #pragma unroll
                for (int it = 0; it < 8; ++it) {
                    int r = wrp + it * 8;
                    float4 v = __ldg((const float4*)(g_fused +
                                    ((size_t)b * EE + cb + r) * HWN + tileTok) + c8);
                    float a = s_attn[cb + r];
                    uint16_t h0, l0, h1, l1, h2, l2, h3, l3;
                    f16_split(v.x * a, h0, l0);
                    f16_split(v.y * a, h1, l1);
                    f16_split(v.z * a, h2, l2);
                    f16_split(v.w * a, h3, l3);
                    uint2 hh = make_uint2((uint32_t)h0 | ((uint32_t)h1 << 16),
                                          (uint32_t)h2 | ((uint32_t)h3 << 16));
                    uint2 ll = make_uint2((uint32_t)l0 | ((uint32_t)l1 << 16),
                                          (uint32_t)l2 | ((uint32_t)l3 << 16));
                    *(uint2*)((char*)Ah + r * AROW + c8 * 8) = hh;
                    *(uint2*)((char*)Al + r * AROW + c8 * 8) = ll;
                }
            }

            CP_COMMIT();
            CP_WAIT0();
            __syncthreads();

            // ---- compute: 4 k16 steps ----
            #pragma unroll
            for (int k16 = 0; k16 < 4; ++k16) {
                const uint32_t kb = k16 * 16;
                uint32_t ahf[2][4], alf[2][4];
                #pragma unroll
                for (int mi = 0; mi < 2; ++mi) {
                    uint32_t ao = (kb + aRow0) * AROW + (aCol0 + mi * 16) * 2;
                    LDSM_X4T(ahf[mi][0], ahf[mi][1], ahf[mi][2], ahf[mi][3], sAh + ao);
                    LDSM_X4T(alf[mi][0], alf[mi][1], alf[mi][2], alf[mi][3], sAl + ao);
                }
                #pragma unroll
                for (int nh = 0; nh < 4; ++nh) {
                    uint32_t wo = (wRow0 + nh * 16) * WROW + (kb + wKoff) * 2;
                    uint32_t whf[4];
                    LDSM_X4(whf[0], whf[1], whf[2], whf[3], sWh + wo);
                    #pragma unroll
                    for (int mi = 0; mi < 2; ++mi) {
                        mma_f16(acc[mi][nh * 2],     ahf[mi], whf[0], whf[1]);
                        mma_f16(acc[mi][nh * 2 + 1], ahf[mi], whf[2], whf[3]);
                        mma_f16(acc[mi][nh * 2],     alf[mi], whf[0], whf[1]);
                        mma_f16(acc[mi][nh * 2 + 1], alf[mi], whf[2], whf[3]);
                    }
                    if (TAPS == 0) {
                        uint32_t wlf[4];
                        LDSM_X4(wlf[0], wlf[1], wlf[2], wlf[3], sWl + wo);
                        #pragma unroll
                        for (int mi = 0; mi < 2; ++mi) {
                            mma_f16(acc[mi][nh * 2],     ahf[mi], wlf[0], wlf[1]);
                            mma_f16(acc[mi][nh * 2 + 1], ahf[mi], wlf[2], wlf[3]);
                        }
                    }
                }
            }
        }
    }

    // ---- epilogue (proven) ----
    const int r0 = wm * 32 + (lane >> 2);
    if (TAPS > 0) {
        #pragma unroll
        for (int ni = 0; ni < 8; ++ni) {
            int ch = wn * 64 + ni * 8 + (lane & 3) * 2;
            float bv0 = __ldg(bias + ch), bv1 = __ldg(bias + ch + 1);
            float* d0 = g_fused + ((size_t)b * EE + c0 + ch) * HWN + tileTok;
            float* d1 = d0 + HWN;
            #pragma unroll
            for (int mi = 0; mi < 2; ++mi) {
                int m = r0 + mi * 16;
                d0[m]     = acc[mi][ni][0] + bv0;
                d1[m]     = acc[mi][ni][1] + bv1;
                d0[m + 8] = acc[mi][ni][2] + bv0;
                d1[m + 8] = acc[mi][ni][3] + bv1;
            }
        }
    } else {
        #pragma unroll
        for (int ni = 0; ni < 8; ++ni) {
            int chl = wn * 64 + ni * 8 + (lane & 3) * 2;
            int e = nb * 128 + chl;
            float bv0 = __ldg(bias + e), bv1 = __ldg(bias + e + 1);
            #pragma unroll
            for (int mi = 0; mi < 2; ++mi) {
                int m = r0 + mi * 16;
                float* da = out + ((size_t)b * HWN + tileTok + m) * EE + e;
                float* db = out + ((size_t)b * HWN + tileTok + m + 8) * EE + e;
                *(float2*)da = make_float2(acc[mi][ni][0] + bv0, acc[mi][ni][1] + bv1);
                *(float2*)db = make_float2(acc[mi][ni][2] + bv0, acc[mi][ni][3] + bv1);
            }
        }
    }
}

// ---------------- pool / attention / layernorm (unchanged, passing) ------
__global__ void pool_kernel() {
    int row = blockIdx.x;
    const float* p = g_fused + (size_t)row * HWN;
    int tid = threadIdx.x;
    float s = 0.f, m = -INFINITY;
    for (int i = tid; i < HWN; i += 256) { float v = p[i]; s += v; m = fmaxf(m, v); }
    __shared__ float ss[256], sm[256];
    ss[tid] = s; sm[tid] = m;
    __syncthreads();
    for (int st = 128; st > 0; st >>= 1) {
        if (tid < st) { ss[tid] += ss[tid + st]; sm[tid] = fmaxf(sm[tid], sm[tid + st]); }
        __syncthreads();
    }
    if (tid == 0) { g_avg[row] = ss[0] * (1.f / HWN); g_max[row] = sm[0]; }
}

__global__ void attn_kernel(const float* __restrict__ cw1, const float* __restrict__ cw2) {
    __shared__ float h1[24], h2[24];
    int b = blockIdx.x;
    int tid = threadIdx.x;
    if (tid < 24) {
        float s = 0.f;
        const float* w = cw1 + tid * EE;
        const float* v = g_avg + b * EE;
        #pragma unroll 4
        for (int c = 0; c < EE; ++c) s += v[c] * w[c];
        h1[tid] = fmaxf(s, 0.f);
    } else if (tid < 48) {
        int j = tid - 24;
        float s = 0.f;
        const float* w = cw1 + j * EE;
        const float* v = g_max + b * EE;
        #pragma unroll 4
        for (int c = 0; c < EE; ++c) s += v[c] * w[c];
        h2[j] = fmaxf(s, 0.f);
    }
    __syncthreads();
    float s = 0.f;
    const float* w = cw2 + tid * 24;
    #pragma unroll
    for (int j = 0; j < 24; ++j) s += (h1[j] + h2[j]) * w[j];
    g_attn[b * EE + tid] = 1.f / (1.f + expf(-s));
}

__global__ void ln_kernel(float* __restrict__ out, const float* __restrict__ g,
                          const float* __restrict__ beta) {
    int tokrow = blockIdx.x;
    float* p = out + (size_t)tokrow * EE;
    int tid = threadIdx.x;
    float v0 = p[tid], v1 = p[tid + 128], v2 = p[tid + 256];
    float s = v0 + v1 + v2;
    float q = v0 * v0 + v1 * v1 + v2 * v2;
    #pragma unroll
    for (int off = 16; off > 0; off >>= 1) {
        s += __shfl_down_sync(0xffffffffu, s, off);
        q += __shfl_down_sync(0xffffffffu, q, off);
    }
    __shared__ float rs[4], rq[4];
    __shared__ float smean, srstd;
    int wid = tid >> 5, lane = tid & 31;
    if (lane == 0) { rs[wid] = s; rq[wid] = q; }
    __syncthreads();
    if (tid == 0) {
        float ts = rs[0] + rs[1] + rs[2] + rs[3];
        float tq = rq[0] + rq[1] + rq[2] + rq[3];
        float mean = ts * (1.f / EE);
        float var  = tq * (1.f / EE) - mean * mean;
        smean = mean;
        srstd = rsqrtf(var + 1e-5f);
    }
    __syncthreads();
    float mean = smean, rstd = srstd;
    p[tid]       = (v0 - mean) * rstd * g[tid]       + beta[tid];
    p[tid + 128] = (v1 - mean) * rstd * g[tid + 128] + beta[tid + 128];
    p[tid + 256] = (v2 - mean) * rstd * g[tid + 256] + beta[tid + 256];
}

// ---------------- launch ---------------------------------------------------
extern "C" void kernel_launch(void* const* d_in, const int* in_sizes, int n_in,
                              void* d_out, int out_size) {
    const float* x   = (const float*)d_in[0];
    const float* w3  = (const float*)d_in[1];
    const float* b3  = (const float*)d_in[2];
    const float* w5  = (const float*)d_in[3];
    const float* b5  = (const float*)d_in[4];
    const float* w7  = (const float*)d_in[5];
    const float* b7  = (const float*)d_in[6];
    const float* cw1 = (const float*)d_in[7];
    const float* cw2 = (const float*)d_in[8];
    const float* fw  = (const float*)d_in[9];
    const float* fb  = (const float*)d_in[10];
    const float* lng = (const float*)d_in[11];
    const float* lnb = (const float*)d_in[12];
    float* out = (float*)d_out;

    cudaFuncSetAttribute(mm_kernel<3>, cudaFuncAttributeMaxDynamicSharedMemorySize, SMEM_SZ);
    cudaFuncSetAttribute(mm_kernel<5>, cudaFuncAttributeMaxDynamicSharedMemorySize, SMEM_SZ);
    cudaFuncSetAttribute(mm_kernel<7>, cudaFuncAttributeMaxDynamicSharedMemorySize, SMEM_SZ);
    cudaFuncSetAttribute(mm_kernel<0>, cudaFuncAttributeMaxDynamicSharedMemorySize, SMEM_SZ);

    prep_x<<<(int)((4ull * NPL + 255) / 256), 256>>>(x);
    prep_wc<3><<<(9  * 16384 + 255) / 256, 256>>>(w3);
    prep_wc<5><<<(25 * 16384 + 255) / 256, 256>>>(w5);
    prep_wc<7><<<(49 * 16384 + 255) / 256, 256>>>(w7);
    prep_wf<<<(EE * EE + 255) / 256, 256>>>(fw);

    dim3 cgrid(HWN / 128, BATCH);
    mm_kernel<3><<<cgrid, 256, SMEM_SZ>>>(b3, nullptr, 0);
    mm_kernel<5><<<cgrid, 256, SMEM_SZ>>>(b5, nullptr, EB);
    mm_kernel<7><<<cgrid, 256, SMEM_SZ>>>(b7, nullptr, 2 * EB);

    pool_kernel<<<BATCH * EE, 256>>>();
    attn_kernel<<<BATCH, EE>>>(cw1, cw2);

    dim3 ggrid(HWN / 128, BATCH, 3);
    mm_kernel<0><<<ggrid, 256, SMEM_SZ>>>(fb, out, 0);

    ln_kernel<<<BATCH * HWN, 128>>>(out, lng, lnb);
}

// round 13
// speedup vs baseline: 2.1755x; 1.3235x over previous
#include <cuda_runtime.h>
#include <cuda_fp16.h>
#include <cstdint>
#include <math.h>

#define BATCH 32
#define CIN   128
#define HWN   4096
#define EB    128
#define EE    384
#define PROW  72
#define PIMG  5184      // 72*72 padded image (4-border)
#define NPL   ((size_t)BATCH * CIN * PIMG)

// SMEM layout (bytes): A rows=[k][tok] 272B, W rows=[n][k] 144B
#define AROW  272
#define WROW  144
#define OFF_AH   0
#define OFF_AL   17408
#define OFF_WH   34816
#define OFF_WL   53248
#define OFF_ATTN 71680
#define SMEM_SZ  73728

// ---------------- device scratch (no allocation allowed) ----------------
__device__ float    g_fused[(size_t)BATCH * EE * HWN];   // [b][c][hw]
__device__ __align__(16) uint16_t g_ph[4][NPL];          // fp16 planes, shift 0..3
__device__ uint16_t g_w3h[9  * 128 * 128];               // [tap][o][ci], fp16
__device__ uint16_t g_w5h[25 * 128 * 128];
__device__ uint16_t g_w7h[49 * 128 * 128];
__device__ uint16_t g_wfh[EE * EE], g_wfl[EE * EE];      // fusion: hi + lo
__device__ float    g_avg[BATCH * EE];
__device__ float    g_max[BATCH * EE];
__device__ float    g_attn[BATCH * EE];

// ---------------- helpers -------------------------------------------------
__device__ __forceinline__ uint32_t smem_u32(const void* p) {
    uint32_t a;
    asm("{ .reg .u64 t; cvta.to.shared.u64 t, %1; cvt.u32.u64 %0, t; }" : "=r"(a) : "l"(p));
    return a;
}

#define LDSM_X4(r0, r1, r2, r3, addr) \
    asm volatile("ldmatrix.sync.aligned.m8n8.x4.shared.b16 {%0,%1,%2,%3}, [%4];" \
                 : "=r"(r0), "=r"(r1), "=r"(r2), "=r"(r3) : "r"(addr))

#define LDSM_X4T(r0, r1, r2, r3, addr) \
    asm volatile("ldmatrix.sync.aligned.m8n8.x4.trans.shared.b16 {%0,%1,%2,%3}, [%4];" \
                 : "=r"(r0), "=r"(r1), "=r"(r2), "=r"(r3) : "r"(addr))

__device__ __forceinline__ void cp8(uint32_t dst, const void* src) {
    asm volatile("cp.async.ca.shared.global [%0], [%1], 8;" :: "r"(dst), "l"(src));
}
__device__ __forceinline__ void cp16(uint32_t dst, const void* src) {
    asm volatile("cp.async.cg.shared.global [%0], [%1], 16;" :: "r"(dst), "l"(src));
}
#define CP_COMMIT() asm volatile("cp.async.commit_group;" ::: "memory")
#define CP_WAIT0()  asm volatile("cp.async.wait_group 0;" ::: "memory")

__device__ __forceinline__ void mma_f16(float* c, const uint32_t* a,
                                        uint32_t b0, uint32_t b1) {
    asm volatile(
        "mma.sync.aligned.m16n8k16.row.col.f32.f16.f16.f32 "
        "{%0,%1,%2,%3}, {%4,%5,%6,%7}, {%8,%9}, {%0,%1,%2,%3};"
        : "+f"(c[0]), "+f"(c[1]), "+f"(c[2]), "+f"(c[3])
        : "r"(a[0]), "r"(a[1]), "r"(a[2]), "r"(a[3]), "r"(b0), "r"(b1));
}

__device__ __forceinline__ void f16_split(float v, uint16_t& h, uint16_t& l) {
    __half hh = __float2half_rn(v);
    float rem = v - __half2float(hh);
    __half hl = __float2half_rn(rem);
    h = *reinterpret_cast<uint16_t*>(&hh);
    l = *reinterpret_cast<uint16_t*>(&hl);
}
__device__ __forceinline__ uint16_t f16_hi(float v) {
    __half hh = __float2half_rn(v);
    return *reinterpret_cast<uint16_t*>(&hh);
}

// ---------------- prep kernels --------------------------------------------
// Padded shifted planes: g_ph[s][bc][r][j] = f16(x[bc][r-4][j-4+s]), zero outside.
__global__ void prep_x(const float* __restrict__ x) {
    size_t idx = (size_t)blockIdx.x * blockDim.x + threadIdx.x;
    if (idx >= 4ull * NPL) return;
    int    s   = (int)(idx / NPL);
    size_t rem = idx % NPL;
    size_t bc  = rem / PIMG;
    int    p   = (int)(rem % PIMG);
    int r = p / PROW, j = p % PROW;
    int oy = r - 4, ox = j - 4 + s;
    float v = 0.f;
    if ((unsigned)oy < 64u && (unsigned)ox < 64u)
        v = x[bc * HWN + oy * 64 + ox];
    g_ph[s][rem] = f16_hi(v);
}

template<int TAPS>
__global__ void prep_wc(const float* __restrict__ w) {
    uint16_t* wh = (TAPS == 3) ? g_w3h : (TAPS == 5) ? g_w5h : g_w7h;
    int idx = blockIdx.x * blockDim.x + threadIdx.x;
    if (idx >= TAPS * TAPS * 128 * 128) return;
    int tap  = idx >> 14;
    int rest = idx & 16383;
    int o    = rest >> 7;
    int ci   = rest & 127;
    wh[idx] = f16_hi(w[(o * CIN + ci) * (TAPS * TAPS) + tap]);
}

__global__ void prep_wf(const float* __restrict__ fw) {
    int idx = blockIdx.x * blockDim.x + threadIdx.x;
    if (idx >= EE * EE) return;
    uint16_t h, l; f16_split(fw[idx], h, l);
    g_wfh[idx] = h;
    g_wfl[idx] = l;
}

// ---------------- tensor-core matmul kernel (mma.sync fp16) ---------------
// Convs (TAPS 3/5/7): pure fp16 single-term Ah*Wh.  Fusion (TAPS 0): 3-term split.
// CTA 128x128, 8 warps (4M x 2N), warp tile 32x64, K chunks 64, cp.async staging.
template<int TAPS>
__global__ __launch_bounds__(256, 2) void mm_kernel(const float* __restrict__ bias,
                                                    float* __restrict__ out, int c0) {
    extern __shared__ char smem[];
    uint16_t* Ah = (uint16_t*)(smem + OFF_AH);
    uint16_t* Al = (uint16_t*)(smem + OFF_AL);
    float* s_attn = (float*)(smem + OFF_ATTN);

    const int tid = threadIdx.x;
    const int b   = blockIdx.y;
    const int tileTok = blockIdx.x * 128;
    const int nb = (TAPS == 0) ? blockIdx.z : 0;

    if (TAPS == 0)
        for (int i = tid; i < EE; i += 256) s_attn[i] = g_attn[b * EE + i];

    const int lane = tid & 31, wid = tid >> 5;
    const int wm = wid & 3, wn = wid >> 2;
    const int oL = tid & 127, hf = tid >> 7;

    float acc[2][8][4];
    #pragma unroll
    for (int mi = 0; mi < 2; ++mi)
        #pragma unroll
        for (int ni = 0; ni < 8; ++ni)
            #pragma unroll
            for (int q = 0; q < 4; ++q) acc[mi][ni][q] = 0.f;

    const uint32_t sAh = smem_u32(smem + OFF_AH), sAl = smem_u32(smem + OFF_AL);
    const uint32_t sWh = smem_u32(smem + OFF_WH), sWl = smem_u32(smem + OFF_WL);

    const int NT  = (TAPS == 0) ? 1 : TAPS * TAPS;
    const int NCC = (TAPS == 0) ? 6 : 2;   // 64-wide K chunks per tap
    const uint16_t* gwh = (TAPS == 3) ? g_w3h : (TAPS == 5) ? g_w5h
                         : (TAPS == 7) ? g_w7h : g_wfh;

    // ldmatrix addresses (proven maps)
    const uint32_t aRow0 = (lane & 7) + ((lane >> 4) << 3);
    const uint32_t aCol0 = wm * 32 + ((lane >> 3) & 1) * 8;
    const uint32_t wRow0 = wn * 64 + (lane & 7) + ((lane >> 4) << 3);
    const uint32_t wKoff = ((lane >> 3) & 1) << 3;

    // staging maps (256 threads)
    const int wrp = tid >> 5;        // A: k-row base (stride 8) / warp id
    const int c8  = tid & 31;        // A: 8B col -> tokens 4*c8..+3
    const int pyB = tileTok >> 6;

    for (int tap = 0; tap < NT; ++tap) {
        const uint16_t* ph = nullptr;
        size_t rjBase = 0;
        if (TAPS > 0) {
            int dy = tap / TAPS - TAPS / 2, dx = tap % TAPS - TAPS / 2;
            int s  = dx & 3;
            int d4 = dx - s;                         // -4 or 0
            int trow = c8 >> 4;                      // 0/1 within 128-token tile
            int px0  = (4 * c8) & 63;
            int r = pyB + trow + dy + 4;             // padded row
            int j = px0 + 4 + d4;                    // padded col, mult of 4
            rjBase = (size_t)r * PROW + j;
            ph = g_ph[s];
        }

        for (int cc = 0; cc < NCC; ++cc) {
            __syncthreads();   // previous chunk's compute done

            // ---- stage A: [64 k][128 tok] via cp.async 8B (conv, hi only) ----
            if (TAPS > 0) {
                size_t bcbase = (size_t)(b * CIN + cc * 64 + wrp) * PIMG + rjBase;
                uint32_t dh = sAh + wrp * AROW + c8 * 8;
                #pragma unroll
                for (int it = 0; it < 8; ++it) {
                    cp8(dh, ph + bcbase);
                    bcbase += 8ull * PIMG;
                    dh += 8 * AROW;
                }
            }

            // ---- stage W hi (and lo for fusion) via cp.async 16B ----
            {
                size_t roff = (TAPS == 0)
                    ? ((size_t)(nb * 128 + oL) * EE + cc * 64 + hf * 32)
                    : ((size_t)(tap * 128 + oL) * 128 + cc * 64 + hf * 32);
                uint32_t dwh = sWh + oL * WROW + hf * 64;
                #pragma unroll
                for (int jj = 0; jj < 4; ++jj)
                    cp16(dwh + jj * 16, gwh + roff + jj * 8);
                if (TAPS == 0) {
                    uint32_t dwl = sWl + oL * WROW + hf * 64;
                    #pragma unroll
                    for (int jj = 0; jj < 4; ++jj)
                        cp16(dwl + jj * 16, g_wfl + roff + jj * 8);
                }
            }

            // ---- stage A (fusion): attention gate + f16_split in regs ----
            if (TAPS == 0) {
                const int cb = cc * 64;
                #pragma unroll
                for (int it = 0; it < 8; ++it) {
                    int r = wrp + it * 8;
                    float4 v = __ldg((const float4*)(g_fused +
                                    ((size_t)b * EE + cb + r) * HWN + tileTok) + c8);
                    float a = s_attn[cb + r];
                    uint16_t h0, l0, h1, l1, h2, l2, h3, l3;
                    f16_split(v.x * a, h0, l0);
                    f16_split(v.y * a, h1, l1);
                    f16_split(v.z * a, h2, l2);
                    f16_split(v.w * a, h3, l3);
                    uint2 hh = make_uint2((uint32_t)h0 | ((uint32_t)h1 << 16),
                                          (uint32_t)h2 | ((uint32_t)h3 << 16));
                    uint2 ll = make_uint2((uint32_t)l0 | ((uint32_t)l1 << 16),
                                          (uint32_t)l2 | ((uint32_t)l3 << 16));
                    *(uint2*)((char*)Ah + r * AROW + c8 * 8) = hh;
                    *(uint2*)((char*)Al + r * AROW + c8 * 8) = ll;
                }
            }

            CP_COMMIT();
            CP_WAIT0();
            __syncthreads();

            // ---- compute: 4 k16 steps ----
            #pragma unroll
            for (int k16 = 0; k16 < 4; ++k16) {
                const uint32_t kb = k16 * 16;
                uint32_t ahf[2][4];
                #pragma unroll
                for (int mi = 0; mi < 2; ++mi) {
                    uint32_t ao = (kb + aRow0) * AROW + (aCol0 + mi * 16) * 2;
                    LDSM_X4T(ahf[mi][0], ahf[mi][1], ahf[mi][2], ahf[mi][3], sAh + ao);
                }
                uint32_t alf[2][4];
                if (TAPS == 0) {
                    #pragma unroll
                    for (int mi = 0; mi < 2; ++mi) {
                        uint32_t ao = (kb + aRow0) * AROW + (aCol0 + mi * 16) * 2;
                        LDSM_X4T(alf[mi][0], alf[mi][1], alf[mi][2], alf[mi][3], sAl + ao);
                    }
                }
                #pragma unroll
                for (int nh = 0; nh < 4; ++nh) {
                    uint32_t wo = (wRow0 + nh * 16) * WROW + (kb + wKoff) * 2;
                    uint32_t whf[4];
                    LDSM_X4(whf[0], whf[1], whf[2], whf[3], sWh + wo);
                    #pragma unroll
                    for (int mi = 0; mi < 2; ++mi) {
                        mma_f16(acc[mi][nh * 2],     ahf[mi], whf[0], whf[1]);
                        mma_f16(acc[mi][nh * 2 + 1], ahf[mi], whf[2], whf[3]);
                    }
                    if (TAPS == 0) {
                        uint32_t wlf[4];
                        LDSM_X4(wlf[0], wlf[1], wlf[2], wlf[3], sWl + wo);
                        #pragma unroll
                        for (int mi = 0; mi < 2; ++mi) {
                            mma_f16(acc[mi][nh * 2],     alf[mi], whf[0], whf[1]);
                            mma_f16(acc[mi][nh * 2 + 1], alf[mi], whf[2], whf[3]);
                            mma_f16(acc[mi][nh * 2],     ahf[mi], wlf[0], wlf[1]);
                            mma_f16(acc[mi][nh * 2 + 1], ahf[mi], wlf[2], wlf[3]);
                        }
                    }
                }
            }
        }
    }

    // ---- epilogue (proven) ----
    const int r0 = wm * 32 + (lane >> 2);
    if (TAPS > 0) {
        #pragma unroll
        for (int ni = 0; ni < 8; ++ni) {
            int ch = wn * 64 + ni * 8 + (lane & 3) * 2;
            float bv0 = __ldg(bias + ch), bv1 = __ldg(bias + ch + 1);
            float* d0 = g_fused + ((size_t)b * EE + c0 + ch) * HWN + tileTok;
            float* d1 = d0 + HWN;
            #pragma unroll
            for (int mi = 0; mi < 2; ++mi) {
                int m = r0 + mi * 16;
                d0[m]     = acc[mi][ni][0] + bv0;
                d1[m]     = acc[mi][ni][1] + bv1;
                d0[m + 8] = acc[mi][ni][2] + bv0;
                d1[m + 8] = acc[mi][ni][3] + bv1;
            }
        }
    } else {
        #pragma unroll
        for (int ni = 0; ni < 8; ++ni) {
            int chl = wn * 64 + ni * 8 + (lane & 3) * 2;
            int e = nb * 128 + chl;
            float bv0 = __ldg(bias + e), bv1 = __ldg(bias + e + 1);
            #pragma unroll
            for (int mi = 0; mi < 2; ++mi) {
                int m = r0 + mi * 16;
                float* da = out + ((size_t)b * HWN + tileTok + m) * EE + e;
                float* db = out + ((size_t)b * HWN + tileTok + m + 8) * EE + e;
                *(float2*)da = make_float2(acc[mi][ni][0] + bv0, acc[mi][ni][1] + bv1);
                *(float2*)db = make_float2(acc[mi][ni][2] + bv0, acc[mi][ni][3] + bv1);
            }
        }
    }
}

// ---------------- pool / attention / layernorm (unchanged, passing) ------
__global__ void pool_kernel() {
    int row = blockIdx.x;
    const float* p = g_fused + (size_t)row * HWN;
    int tid = threadIdx.x;
    float s = 0.f, m = -INFINITY;
    for (int i = tid; i < HWN; i += 256) { float v = p[i]; s += v; m = fmaxf(m, v); }
    __shared__ float ss[256], sm[256];
    ss[tid] = s; sm[tid] = m;
    __syncthreads();
    for (int st = 128; st > 0; st >>= 1) {
        if (tid < st) { ss[tid] += ss[tid + st]; sm[tid] = fmaxf(sm[tid], sm[tid + st]); }
        __syncthreads();
    }
    if (tid == 0) { g_avg[row] = ss[0] * (1.f / HWN); g_max[row] = sm[0]; }
}

__global__ void attn_kernel(const float* __restrict__ cw1, const float* __restrict__ cw2) {
    __shared__ float h1[24], h2[24];
    int b = blockIdx.x;
    int tid = threadIdx.x;
    if (tid < 24) {
        float s = 0.f;
        const float* w = cw1 + tid * EE;
        const float* v = g_avg + b * EE;
        #pragma unroll 4
        for (int c = 0; c < EE; ++c) s += v[c] * w[c];
        h1[tid] = fmaxf(s, 0.f);
    } else if (tid < 48) {
        int j = tid - 24;
        float s = 0.f;
        const float* w = cw1 + j * EE;
        const float* v = g_max + b * EE;
        #pragma unroll 4
        for (int c = 0; c < EE; ++c) s += v[c] * w[c];
        h2[j] = fmaxf(s, 0.f);
    }
    __syncthreads();
    float s = 0.f;
    const float* w = cw2 + tid * 24;
    #pragma unroll
    for (int j = 0; j < 24; ++j) s += (h1[j] + h2[j]) * w[j];
    g_attn[b * EE + tid] = 1.f / (1.f + expf(-s));
}

__global__ void ln_kernel(float* __restrict__ out, const float* __restrict__ g,
                          const float* __restrict__ beta) {
    int tokrow = blockIdx.x;
    float* p = out + (size_t)tokrow * EE;
    int tid = threadIdx.x;
    float v0 = p[tid], v1 = p[tid + 128], v2 = p[tid + 256];
    float s = v0 + v1 + v2;
    float q = v0 * v0 + v1 * v1 + v2 * v2;
    #pragma unroll
    for (int off = 16; off > 0; off >>= 1) {
        s += __shfl_down_sync(0xffffffffu, s, off);
        q += __shfl_down_sync(0xffffffffu, q, off);
    }
    __shared__ float rs[4], rq[4];
    __shared__ float smean, srstd;
    int wid = tid >> 5, lane = tid & 31;
    if (lane == 0) { rs[wid] = s; rq[wid] = q; }
    __syncthreads();
    if (tid == 0) {
        float ts = rs[0] + rs[1] + rs[2] + rs[3];
        float tq = rq[0] + rq[1] + rq[2] + rq[3];
        float mean = ts * (1.f / EE);
        float var  = tq * (1.f / EE) - mean * mean;
        smean = mean;
        srstd = rsqrtf(var + 1e-5f);
    }
    __syncthreads();
    float mean = smean, rstd = srstd;
    p[tid]       = (v0 - mean) * rstd * g[tid]       + beta[tid];
    p[tid + 128] = (v1 - mean) * rstd * g[tid + 128] + beta[tid + 128];
    p[tid + 256] = (v2 - mean) * rstd * g[tid + 256] + beta[tid + 256];
}

// ---------------- launch ---------------------------------------------------
extern "C" void kernel_launch(void* const* d_in, const int* in_sizes, int n_in,
                              void* d_out, int out_size) {
    const float* x   = (const float*)d_in[0];
    const float* w3  = (const float*)d_in[1];
    const float* b3  = (const float*)d_in[2];
    const float* w5  = (const float*)d_in[3];
    const float* b5  = (const float*)d_in[4];
    const float* w7  = (const float*)d_in[5];
    const float* b7  = (const float*)d_in[6];
    const float* cw1 = (const float*)d_in[7];
    const float* cw2 = (const float*)d_in[8];
    const float* fw  = (const float*)d_in[9];
    const float* fb  = (const float*)d_in[10];
    const float* lng = (const float*)d_in[11];
    const float* lnb = (const float*)d_in[12];
    float* out = (float*)d_out;

    cudaFuncSetAttribute(mm_kernel<3>, cudaFuncAttributeMaxDynamicSharedMemorySize, SMEM_SZ);
    cudaFuncSetAttribute(mm_kernel<5>, cudaFuncAttributeMaxDynamicSharedMemorySize, SMEM_SZ);
    cudaFuncSetAttribute(mm_kernel<7>, cudaFuncAttributeMaxDynamicSharedMemorySize, SMEM_SZ);
    cudaFuncSetAttribute(mm_kernel<0>, cudaFuncAttributeMaxDynamicSharedMemorySize, SMEM_SZ);

    prep_x<<<(int)((4ull * NPL + 255) / 256), 256>>>(x);
    prep_wc<3><<<(9  * 16384 + 255) / 256, 256>>>(w3);
    prep_wc<5><<<(25 * 16384 + 255) / 256, 256>>>(w5);
    prep_wc<7><<<(49 * 16384 + 255) / 256, 256>>>(w7);
    prep_wf<<<(EE * EE + 255) / 256, 256>>>(fw);

    dim3 cgrid(HWN / 128, BATCH);
    mm_kernel<3><<<cgrid, 256, SMEM_SZ>>>(b3, nullptr, 0);
    mm_kernel<5><<<cgrid, 256, SMEM_SZ>>>(b5, nullptr, EB);
    mm_kernel<7><<<cgrid, 256, SMEM_SZ>>>(b7, nullptr, 2 * EB);

    pool_kernel<<<BATCH * EE, 256>>>();
    attn_kernel<<<BATCH, EE>>>(cw1, cw2);

    dim3 ggrid(HWN / 128, BATCH, 3);
    mm_kernel<0><<<ggrid, 256, SMEM_SZ>>>(fb, out, 0);

    ln_kernel<<<BATCH * HWN, 128>>>(out, lng, lnb);
}

// round 14
// speedup vs baseline: 2.3626x; 1.0860x over previous
#include <cuda_runtime.h>
#include <cuda_fp16.h>
#include <cstdint>
#include <math.h>

#define BATCH 32
#define CIN   128
#define HWN   4096
#define EB    128
#define EE    384
#define PROW  72
#define PIMG  5184      // 72*72 padded image (4-border)
#define NPL   ((size_t)BATCH * CIN * PIMG)

// SMEM layout (bytes): A rows=[k][tok] 272B, W rows=[n][k] 144B
#define AROW  272
#define WROW  144
#define OFF_AH   0
#define OFF_AL   17408
#define OFF_WH   34816
#define OFF_WL   53248
#define OFF_ATTN 71680
#define SMEM_SZ  73728

// ---------------- device scratch (no allocation allowed) ----------------
__device__ float    g_fused[(size_t)BATCH * EE * HWN];   // [b][c][hw]
__device__ __align__(16) uint16_t g_ph[4][NPL];          // fp16 planes, shift 0..3
__device__ uint16_t g_w3h[9  * 128 * 128];               // [tap][o][ci], fp16
__device__ uint16_t g_w5h[25 * 128 * 128];
__device__ uint16_t g_w7h[49 * 128 * 128];
__device__ uint16_t g_wfh[EE * EE];                      // fusion weights fp16
__device__ float    g_avg[BATCH * EE];
__device__ float    g_max[BATCH * EE];
__device__ float    g_attn[BATCH * EE];

// ---------------- helpers -------------------------------------------------
__device__ __forceinline__ uint32_t smem_u32(const void* p) {
    uint32_t a;
    asm("{ .reg .u64 t; cvta.to.shared.u64 t, %1; cvt.u32.u64 %0, t; }" : "=r"(a) : "l"(p));
    return a;
}

#define LDSM_X4(r0, r1, r2, r3, addr) \
    asm volatile("ldmatrix.sync.aligned.m8n8.x4.shared.b16 {%0,%1,%2,%3}, [%4];" \
                 : "=r"(r0), "=r"(r1), "=r"(r2), "=r"(r3) : "r"(addr))

#define LDSM_X4T(r0, r1, r2, r3, addr) \
    asm volatile("ldmatrix.sync.aligned.m8n8.x4.trans.shared.b16 {%0,%1,%2,%3}, [%4];" \
                 : "=r"(r0), "=r"(r1), "=r"(r2), "=r"(r3) : "r"(addr))

__device__ __forceinline__ void cp8(uint32_t dst, const void* src) {
    asm volatile("cp.async.ca.shared.global [%0], [%1], 8;" :: "r"(dst), "l"(src));
}
__device__ __forceinline__ void cp16(uint32_t dst, const void* src) {
    asm volatile("cp.async.cg.shared.global [%0], [%1], 16;" :: "r"(dst), "l"(src));
}
#define CP_COMMIT() asm volatile("cp.async.commit_group;" ::: "memory")
#define CP_WAIT0()  asm volatile("cp.async.wait_group 0;" ::: "memory")

__device__ __forceinline__ void mma_f16(float* c, const uint32_t* a,
                                        uint32_t b0, uint32_t b1) {
    asm volatile(
        "mma.sync.aligned.m16n8k16.row.col.f32.f16.f16.f32 "
        "{%0,%1,%2,%3}, {%4,%5,%6,%7}, {%8,%9}, {%0,%1,%2,%3};"
        : "+f"(c[0]), "+f"(c[1]), "+f"(c[2]), "+f"(c[3])
        : "r"(a[0]), "r"(a[1]), "r"(a[2]), "r"(a[3]), "r"(b0), "r"(b1));
}

__device__ __forceinline__ uint16_t f16_hi(float v) {
    __half hh = __float2half_rn(v);
    return *reinterpret_cast<uint16_t*>(&hh);
}

// ---------------- prep kernels --------------------------------------------
// Padded shifted planes: g_ph[s][bc][r][j] = f16(x[bc][r-4][j-4+s]), zero outside.
__global__ void prep_x(const float* __restrict__ x) {
    size_t idx = (size_t)blockIdx.x * blockDim.x + threadIdx.x;
    if (idx >= 4ull * NPL) return;
    int    s   = (int)(idx / NPL);
    size_t rem = idx % NPL;
    size_t bc  = rem / PIMG;
    int    p   = (int)(rem % PIMG);
    int r = p / PROW, j = p % PROW;
    int oy = r - 4, ox = j - 4 + s;
    float v = 0.f;
    if ((unsigned)oy < 64u && (unsigned)ox < 64u)
        v = x[bc * HWN + oy * 64 + ox];
    g_ph[s][rem] = f16_hi(v);
}

template<int TAPS>
__global__ void prep_wc(const float* __restrict__ w) {
    uint16_t* wh = (TAPS == 3) ? g_w3h : (TAPS == 5) ? g_w5h : g_w7h;
    int idx = blockIdx.x * blockDim.x + threadIdx.x;
    if (idx >= TAPS * TAPS * 128 * 128) return;
    int tap  = idx >> 14;
    int rest = idx & 16383;
    int o    = rest >> 7;
    int ci   = rest & 127;
    wh[idx] = f16_hi(w[(o * CIN + ci) * (TAPS * TAPS) + tap]);
}

__global__ void prep_wf(const float* __restrict__ fw) {
    int idx = blockIdx.x * blockDim.x + threadIdx.x;
    if (idx >= EE * EE) return;
    g_wfh[idx] = f16_hi(fw[idx]);
}

// ---------------- tensor-core matmul kernel (mma.sync fp16, single-term) --
// TAPS 3/5/7: conv branch -> g_fused at channel offset c0.
// TAPS 0: fusion GEMM with attention gate -> out[b][tok][e].
// CTA 128x128, 8 warps (4M x 2N), warp tile 32x64, K chunks 64, cp.async staging.
template<int TAPS>
__global__ __launch_bounds__(256, 2) void mm_kernel(const float* __restrict__ bias,
                                                    float* __restrict__ out, int c0) {
    extern __shared__ char smem[];
    uint16_t* Ah = (uint16_t*)(smem + OFF_AH);
    float* s_attn = (float*)(smem + OFF_ATTN);

    const int tid = threadIdx.x;
    const int b   = blockIdx.y;
    const int tileTok = blockIdx.x * 128;
    const int nb = (TAPS == 0) ? blockIdx.z : 0;

    if (TAPS == 0)
        for (int i = tid; i < EE; i += 256) s_attn[i] = g_attn[b * EE + i];

    const int lane = tid & 31, wid = tid >> 5;
    const int wm = wid & 3, wn = wid >> 2;
    const int oL = tid & 127, hf = tid >> 7;

    float acc[2][8][4];
    #pragma unroll
    for (int mi = 0; mi < 2; ++mi)
        #pragma unroll
        for (int ni = 0; ni < 8; ++ni)
            #pragma unroll
            for (int q = 0; q < 4; ++q) acc[mi][ni][q] = 0.f;

    const uint32_t sAh = smem_u32(smem + OFF_AH);
    const uint32_t sWh = smem_u32(smem + OFF_WH);

    const int NT  = (TAPS == 0) ? 1 : TAPS * TAPS;
    const int NCC = (TAPS == 0) ? 6 : 2;   // 64-wide K chunks per tap
    const uint16_t* gwh = (TAPS == 3) ? g_w3h : (TAPS == 5) ? g_w5h
                         : (TAPS == 7) ? g_w7h : g_wfh;

    // ldmatrix addresses (proven maps)
    const uint32_t aRow0 = (lane & 7) + ((lane >> 4) << 3);
    const uint32_t aCol0 = wm * 32 + ((lane >> 3) & 1) * 8;
    const uint32_t wRow0 = wn * 64 + (lane & 7) + ((lane >> 4) << 3);
    const uint32_t wKoff = ((lane >> 3) & 1) << 3;

    // staging maps (256 threads)
    const int wrp = tid >> 5;        // A: k-row base (stride 8) / warp id
    const int c8  = tid & 31;        // A: 8B col -> tokens 4*c8..+3
    const int pyB = tileTok >> 6;

    for (int tap = 0; tap < NT; ++tap) {
        const uint16_t* ph = nullptr;
        size_t rjBase = 0;
        if (TAPS > 0) {
            int dy = tap / TAPS - TAPS / 2, dx = tap % TAPS - TAPS / 2;
            int s  = dx & 3;
            int d4 = dx - s;                         // -4 or 0
            int trow = c8 >> 4;                      // 0/1 within 128-token tile
            int px0  = (4 * c8) & 63;
            int r = pyB + trow + dy + 4;             // padded row
            int j = px0 + 4 + d4;                    // padded col, mult of 4
            rjBase = (size_t)r * PROW + j;
            ph = g_ph[s];
        }

        for (int cc = 0; cc < NCC; ++cc) {
            __syncthreads();   // previous chunk's compute done

            // ---- stage A: [64 k][128 tok] via cp.async 8B (conv) ----
            if (TAPS > 0) {
                size_t bcbase = (size_t)(b * CIN + cc * 64 + wrp) * PIMG + rjBase;
                uint32_t dh = sAh + wrp * AROW + c8 * 8;
                #pragma unroll
                for (int it = 0; it < 8; ++it) {
                    cp8(dh, ph + bcbase);
                    bcbase += 8ull * PIMG;
                    dh += 8 * AROW;
                }
            }

            // ---- stage W via cp.async 16B ----
            {
                size_t roff = (TAPS == 0)
                    ? ((size_t)(nb * 128 + oL) * EE + cc * 64 + hf * 32)
                    : ((size_t)(tap * 128 + oL) * 128 + cc * 64 + hf * 32);
                uint32_t dwh = sWh + oL * WROW + hf * 64;
                #pragma unroll
                for (int jj = 0; jj < 4; ++jj)
                    cp16(dwh + jj * 16, gwh + roff + jj * 8);
            }

            // ---- stage A (fusion): attention gate + f16 convert in regs ----
            if (TAPS == 0) {
                const int cb = cc * 64;
                #pragma unroll
                for (int it = 0; it < 8; ++it) {
                    int r = wrp + it * 8;
                    float4 v = __ldg((const float4*)(g_fused +
                                    ((size_t)b * EE + cb + r) * HWN + tileTok) + c8);
                    float a = s_attn[cb + r];
                    uint16_t h0 = f16_hi(v.x * a), h1 = f16_hi(v.y * a);
                    uint16_t h2 = f16_hi(v.z * a), h3 = f16_hi(v.w * a);
                    uint2 hh = make_uint2((uint32_t)h0 | ((uint32_t)h1 << 16),
                                          (uint32_t)h2 | ((uint32_t)h3 << 16));
                    *(uint2*)((char*)Ah + r * AROW + c8 * 8) = hh;
                }
            }

            CP_COMMIT();
            CP_WAIT0();
            __syncthreads();

            // ---- compute: 4 k16 steps, single fp16 term ----
            #pragma unroll
            for (int k16 = 0; k16 < 4; ++k16) {
                const uint32_t kb = k16 * 16;
                uint32_t ahf[2][4];
                #pragma unroll
                for (int mi = 0; mi < 2; ++mi) {
                    uint32_t ao = (kb + aRow0) * AROW + (aCol0 + mi * 16) * 2;
                    LDSM_X4T(ahf[mi][0], ahf[mi][1], ahf[mi][2], ahf[mi][3], sAh + ao);
                }
                #pragma unroll
                for (int nh = 0; nh < 4; ++nh) {
                    uint32_t wo = (wRow0 + nh * 16) * WROW + (kb + wKoff) * 2;
                    uint32_t whf[4];
                    LDSM_X4(whf[0], whf[1], whf[2], whf[3], sWh + wo);
                    #pragma unroll
                    for (int mi = 0; mi < 2; ++mi) {
                        mma_f16(acc[mi][nh * 2],     ahf[mi], whf[0], whf[1]);
                        mma_f16(acc[mi][nh * 2 + 1], ahf[mi], whf[2], whf[3]);
                    }
                }
            }
        }
    }

    // ---- epilogue (proven) ----
    const int r0 = wm * 32 + (lane >> 2);
    if (TAPS > 0) {
        #pragma unroll
        for (int ni = 0; ni < 8; ++ni) {
            int ch = wn * 64 + ni * 8 + (lane & 3) * 2;
            float bv0 = __ldg(bias + ch), bv1 = __ldg(bias + ch + 1);
            float* d0 = g_fused + ((size_t)b * EE + c0 + ch) * HWN + tileTok;
            float* d1 = d0 + HWN;
            #pragma unroll
            for (int mi = 0; mi < 2; ++mi) {
                int m = r0 + mi * 16;
                d0[m]     = acc[mi][ni][0] + bv0;
                d1[m]     = acc[mi][ni][1] + bv1;
                d0[m + 8] = acc[mi][ni][2] + bv0;
                d1[m + 8] = acc[mi][ni][3] + bv1;
            }
        }
    } else {
        #pragma unroll
        for (int ni = 0; ni < 8; ++ni) {
            int chl = wn * 64 + ni * 8 + (lane & 3) * 2;
            int e = nb * 128 + chl;
            float bv0 = __ldg(bias + e), bv1 = __ldg(bias + e + 1);
            #pragma unroll
            for (int mi = 0; mi < 2; ++mi) {
                int m = r0 + mi * 16;
                float* da = out + ((size_t)b * HWN + tileTok + m) * EE + e;
                float* db = out + ((size_t)b * HWN + tileTok + m + 8) * EE + e;
                *(float2*)da = make_float2(acc[mi][ni][0] + bv0, acc[mi][ni][1] + bv1);
                *(float2*)db = make_float2(acc[mi][ni][2] + bv0, acc[mi][ni][3] + bv1);
            }
        }
    }
}

// ---------------- pool / attention / layernorm (unchanged, passing) ------
__global__ void pool_kernel() {
    int row = blockIdx.x;
    const float* p = g_fused + (size_t)row * HWN;
    int tid = threadIdx.x;
    float s = 0.f, m = -INFINITY;
    for (int i = tid; i < HWN; i += 256) { float v = p[i]; s += v; m = fmaxf(m, v); }
    __shared__ float ss[256], sm[256];
    ss[tid] = s; sm[tid] = m;
    __syncthreads();
    for (int st = 128; st > 0; st >>= 1) {
        if (tid < st) { ss[tid] += ss[tid + st]; sm[tid] = fmaxf(sm[tid], sm[tid + st]); }
        __syncthreads();
    }
    if (tid == 0) { g_avg[row] = ss[0] * (1.f / HWN); g_max[row] = sm[0]; }
}

__global__ void attn_kernel(const float* __restrict__ cw1, const float* __restrict__ cw2) {
    __shared__ float h1[24], h2[24];
    int b = blockIdx.x;
    int tid = threadIdx.x;
    if (tid < 24) {
        float s = 0.f;
        const float* w = cw1 + tid * EE;
        const float* v = g_avg + b * EE;
        #pragma unroll 4
        for (int c = 0; c < EE; ++c) s += v[c] * w[c];
        h1[tid] = fmaxf(s, 0.f);
    } else if (tid < 48) {
        int j = tid - 24;
        float s = 0.f;
        const float* w = cw1 + j * EE;
        const float* v = g_max + b * EE;
        #pragma unroll 4
        for (int c = 0; c < EE; ++c) s += v[c] * w[c];
        h2[j] = fmaxf(s, 0.f);
    }
    __syncthreads();
    float s = 0.f;
    const float* w = cw2 + tid * 24;
    #pragma unroll
    for (int j = 0; j < 24; ++j) s += (h1[j] + h2[j]) * w[j];
    g_attn[b * EE + tid] = 1.f / (1.f + expf(-s));
}

__global__ void ln_kernel(float* __restrict__ out, const float* __restrict__ g,
                          const float* __restrict__ beta) {
    int tokrow = blockIdx.x;
    float* p = out + (size_t)tokrow * EE;
    int tid = threadIdx.x;
    float v0 = p[tid], v1 = p[tid + 128], v2 = p[tid + 256];
    float s = v0 + v1 + v2;
    float q = v0 * v0 + v1 * v1 + v2 * v2;
    #pragma unroll
    for (int off = 16; off > 0; off >>= 1) {
        s += __shfl_down_sync(0xffffffffu, s, off);
        q += __shfl_down_sync(0xffffffffu, q, off);
    }
    __shared__ float rs[4], rq[4];
    __shared__ float smean, srstd;
    int wid = tid >> 5, lane = tid & 31;
    if (lane == 0) { rs[wid] = s; rq[wid] = q; }
    __syncthreads();
    if (tid == 0) {
        float ts = rs[0] + rs[1] + rs[2] + rs[3];
        float tq = rq[0] + rq[1] + rq[2] + rq[3];
        float mean = ts * (1.f / EE);
        float var  = tq * (1.f / EE) - mean * mean;
        smean = mean;
        srstd = rsqrtf(var + 1e-5f);
    }
    __syncthreads();
    float mean = smean, rstd = srstd;
    p[tid]       = (v0 - mean) * rstd * g[tid]       + beta[tid];
    p[tid + 128] = (v1 - mean) * rstd * g[tid + 128] + beta[tid + 128];
    p[tid + 256] = (v2 - mean) * rstd * g[tid + 256] + beta[tid + 256];
}

// ---------------- launch ---------------------------------------------------
extern "C" void kernel_launch(void* const* d_in, const int* in_sizes, int n_in,
                              void* d_out, int out_size) {
    const float* x   = (const float*)d_in[0];
    const float* w3  = (const float*)d_in[1];
    const float* b3  = (const float*)d_in[2];
    const float* w5  = (const float*)d_in[3];
    const float* b5  = (const float*)d_in[4];
    const float* w7  = (const float*)d_in[5];
    const float* b7  = (const float*)d_in[6];
    const float* cw1 = (const float*)d_in[7];
    const float* cw2 = (const float*)d_in[8];
    const float* fw  = (const float*)d_in[9];
    const float* fb  = (const float*)d_in[10];
    const float* lng = (const float*)d_in[11];
    const float* lnb = (const float*)d_in[12];
    float* out = (float*)d_out;

    cudaFuncSetAttribute(mm_kernel<3>, cudaFuncAttributeMaxDynamicSharedMemorySize, SMEM_SZ);
    cudaFuncSetAttribute(mm_kernel<5>, cudaFuncAttributeMaxDynamicSharedMemorySize, SMEM_SZ);
    cudaFuncSetAttribute(mm_kernel<7>, cudaFuncAttributeMaxDynamicSharedMemorySize, SMEM_SZ);
    cudaFuncSetAttribute(mm_kernel<0>, cudaFuncAttributeMaxDynamicSharedMemorySize, SMEM_SZ);

    prep_x<<<(int)((4ull * NPL + 255) / 256), 256>>>(x);
    prep_wc<3><<<(9  * 16384 + 255) / 256, 256>>>(w3);
    prep_wc<5><<<(25 * 16384 + 255) / 256, 256>>>(w5);
    prep_wc<7><<<(49 * 16384 + 255) / 256, 256>>>(w7);
    prep_wf<<<(EE * EE + 255) / 256, 256>>>(fw);

    dim3 cgrid(HWN / 128, BATCH);
    mm_kernel<3><<<cgrid, 256, SMEM_SZ>>>(b3, nullptr, 0);
    mm_kernel<5><<<cgrid, 256, SMEM_SZ>>>(b5, nullptr, EB);
    mm_kernel<7><<<cgrid, 256, SMEM_SZ>>>(b7, nullptr, 2 * EB);

    pool_kernel<<<BATCH * EE, 256>>>();
    attn_kernel<<<BATCH, EE>>>(cw1, cw2);

    dim3 ggrid(HWN / 128, BATCH, 3);
    mm_kernel<0><<<ggrid, 256, SMEM_SZ>>>(fb, out, 0);

    ln_kernel<<<BATCH * HWN, 128>>>(out, lng, lnb);
}

// round 16
// speedup vs baseline: 2.4271x; 1.0273x over previous
#include <cuda_runtime.h>
#include <cuda_fp16.h>
#include <cstdint>
#include <math.h>

#define BATCH 32
#define CIN   128
#define HWN   4096
#define EB    128
#define EE    384
#define PROW  72
#define PIMG  5184      // 72*72 padded image (4-border)
#define NPL   ((size_t)BATCH * CIN * PIMG)

// SMEM: two stages, each Ah(64 rows x 272B) + Wh(128 rows x 144B)
#define AROW   272
#define WROW   144
#define WOFF   17408
#define STAGE  36864
#define OFF_ATTN 73728
#define SMEM_SZ  75264

// ---------------- device scratch (no allocation allowed) ----------------
__device__ float    g_fused[(size_t)BATCH * EE * HWN];   // [b][c][hw]
__device__ __align__(16) uint16_t g_ph[4][NPL];          // fp16 planes, shift 0..3
__device__ uint16_t g_w3h[9  * 128 * 128];               // [tap][o][ci], fp16
__device__ uint16_t g_w5h[25 * 128 * 128];
__device__ uint16_t g_w7h[49 * 128 * 128];
__device__ uint16_t g_wfh[EE * EE];                      // fusion weights fp16
__device__ float    g_avg[BATCH * EE];
__device__ float    g_max[BATCH * EE];
__device__ float    g_attn[BATCH * EE];

// ---------------- helpers -------------------------------------------------
__device__ __forceinline__ uint32_t smem_u32(const void* p) {
    uint32_t a;
    asm("{ .reg .u64 t; cvta.to.shared.u64 t, %1; cvt.u32.u64 %0, t; }" : "=r"(a) : "l"(p));
    return a;
}

#define LDSM_X4(r0, r1, r2, r3, addr) \
    asm volatile("ldmatrix.sync.aligned.m8n8.x4.shared.b16 {%0,%1,%2,%3}, [%4];" \
                 : "=r"(r0), "=r"(r1), "=r"(r2), "=r"(r3) : "r"(addr))

#define LDSM_X4T(r0, r1, r2, r3, addr) \
    asm volatile("ldmatrix.sync.aligned.m8n8.x4.trans.shared.b16 {%0,%1,%2,%3}, [%4];" \
                 : "=r"(r0), "=r"(r1), "=r"(r2), "=r"(r3) : "r"(addr))

__device__ __forceinline__ void cp8(uint32_t dst, const void* src) {
    asm volatile("cp.async.ca.shared.global [%0], [%1], 8;" :: "r"(dst), "l"(src));
}
__device__ __forceinline__ void cp16(uint32_t dst, const void* src) {
    asm volatile("cp.async.cg.shared.global [%0], [%1], 16;" :: "r"(dst), "l"(src));
}
#define CP_COMMIT() asm volatile("cp.async.commit_group;" ::: "memory")
#define CP_WAIT0()  asm volatile("cp.async.wait_group 0;" ::: "memory")
#define CP_WAIT1()  asm volatile("cp.async.wait_group 1;" ::: "memory")

__device__ __forceinline__ void mma_f16(float* c, const uint32_t* a,
                                        uint32_t b0, uint32_t b1) {
    asm volatile(
        "mma.sync.aligned.m16n8k16.row.col.f32.f16.f16.f32 "
        "{%0,%1,%2,%3}, {%4,%5,%6,%7}, {%8,%9}, {%0,%1,%2,%3};"
        : "+f"(c[0]), "+f"(c[1]), "+f"(c[2]), "+f"(c[3])
        : "r"(a[0]), "r"(a[1]), "r"(a[2]), "r"(a[3]), "r"(b0), "r"(b1));
}

__device__ __forceinline__ uint16_t f16_hi(float v) {
    __half hh = __float2half_rn(v);
    return *reinterpret_cast<uint16_t*>(&hh);
}

// ---------------- prep kernels --------------------------------------------
__global__ void prep_x(const float* __restrict__ x) {
    size_t idx = (size_t)blockIdx.x * blockDim.x + threadIdx.x;
    if (idx >= 4ull * NPL) return;
    int    s   = (int)(idx / NPL);
    size_t rem = idx % NPL;
    size_t bc  = rem / PIMG;
    int    p   = (int)(rem % PIMG);
    int r = p / PROW, j = p % PROW;
    int oy = r - 4, ox = j - 4 + s;
    float v = 0.f;
    if ((unsigned)oy < 64u && (unsigned)ox < 64u)
        v = x[bc * HWN + oy * 64 + ox];
    g_ph[s][rem] = f16_hi(v);
}

template<int TAPS>
__global__ void prep_wc(const float* __restrict__ w) {
    uint16_t* wh = (TAPS == 3) ? g_w3h : (TAPS == 5) ? g_w5h : g_w7h;
    int idx = blockIdx.x * blockDim.x + threadIdx.x;
    if (idx >= TAPS * TAPS * 128 * 128) return;
    int tap  = idx >> 14;
    int rest = idx & 16383;
    int o    = rest >> 7;
    int ci   = rest & 127;
    wh[idx] = f16_hi(w[(o * CIN + ci) * (TAPS * TAPS) + tap]);
}

__global__ void prep_wf(const float* __restrict__ fw) {
    int idx = blockIdx.x * blockDim.x + threadIdx.x;
    if (idx >= EE * EE) return;
    g_wfh[idx] = f16_hi(fw[idx]);
}

// ---------------- tensor-core matmul kernel (fp16, double-buffered) -------
// TAPS 3/5/7: conv branch -> g_fused at channel offset c0.
// TAPS 0: fusion GEMM with attention gate -> out[b][tok][e].
// CTA 128x128, 8 warps (4M x 2N), warp tile 32x64, K chunks 64.
// 2 SMEM stages; cp.async for chunk q+1 issued before compute of chunk q.
template<int TAPS>
__global__ __launch_bounds__(256, 2) void mm_kernel(const float* __restrict__ bias,
                                                    float* __restrict__ out, int c0) {
    extern __shared__ char smem[];
    float* s_attn = (float*)(smem + OFF_ATTN);

    const int tid = threadIdx.x;
    const int b   = blockIdx.y;
    const int tileTok = blockIdx.x * 128;
    const int nb = (TAPS == 0) ? blockIdx.z : 0;

    if (TAPS == 0) {
        for (int i = tid; i < EE; i += 256) s_attn[i] = g_attn[b * EE + i];
        __syncthreads();   // s_attn visible to all threads before stage(0) reads it
    }

    const int lane = tid & 31, wid = tid >> 5;
    const int wm = wid & 3, wn = wid >> 2;
    const int oL = tid & 127, hf = tid >> 7;

    float acc[2][8][4];
    #pragma unroll
    for (int mi = 0; mi < 2; ++mi)
        #pragma unroll
        for (int ni = 0; ni < 8; ++ni)
            #pragma unroll
            for (int q = 0; q < 4; ++q) acc[mi][ni][q] = 0.f;

    const uint32_t sb0 = smem_u32(smem);
    const int Q = (TAPS == 0) ? 6 : TAPS * TAPS * 2;
    const uint16_t* gwh = (TAPS == 3) ? g_w3h : (TAPS == 5) ? g_w5h
                         : (TAPS == 7) ? g_w7h : g_wfh;

    // ldmatrix lane maps (proven)
    const uint32_t aRow0 = (lane & 7) + ((lane >> 4) << 3);
    const uint32_t aCol0 = wm * 32 + ((lane >> 3) & 1) * 8;
    const uint32_t wRow0 = wn * 64 + (lane & 7) + ((lane >> 4) << 3);
    const uint32_t wKoff = ((lane >> 3) & 1) << 3;

    // staging maps
    const int wrp = tid >> 5;
    const int c8  = tid & 31;
    const int pyB = tileTok >> 6;
    const int trow = c8 >> 4;
    const int px0  = (4 * c8) & 63;

    // ---- stage step: issue async copies for chunk q into buffer q&1 ----
    auto stage = [&](int q) {
        const uint32_t base = sb0 + (uint32_t)(q & 1) * STAGE;
        if (TAPS > 0) {
            const int tap = q >> 1, cc = q & 1;
            const int dy = tap / TAPS - TAPS / 2, dx = tap % TAPS - TAPS / 2;
            const int sh = dx & 3, d4 = dx - sh;
            const uint16_t* ph = g_ph[sh];
            size_t bcbase = (size_t)(b * CIN + cc * 64 + wrp) * PIMG
                          + (size_t)(pyB + trow + dy + 4) * PROW + (px0 + 4 + d4);
            uint32_t dh = base + wrp * AROW + c8 * 8;
            #pragma unroll
            for (int it = 0; it < 8; ++it) {
                cp8(dh, ph + bcbase);
                bcbase += 8ull * PIMG;
                dh += 8 * AROW;
            }
            size_t roff = (size_t)(tap * 128 + oL) * 128 + cc * 64 + hf * 32;
            uint32_t dwh = base + WOFF + oL * WROW + hf * 64;
            #pragma unroll
            for (int jj = 0; jj < 4; ++jj)
                cp16(dwh + jj * 16, gwh + roff + jj * 8);
        } else {
            const int cc = q;
            size_t roff = (size_t)(nb * 128 + oL) * EE + cc * 64 + hf * 32;
            uint32_t dwh = base + WOFF + oL * WROW + hf * 64;
            #pragma unroll
            for (int jj = 0; jj < 4; ++jj)
                cp16(dwh + jj * 16, gwh + roff + jj * 8);
            // A: gate + convert, direct STS
            uint16_t* Ah = (uint16_t*)(smem + (q & 1) * STAGE);
            const int cb = cc * 64;
            #pragma unroll
            for (int it = 0; it < 8; ++it) {
                int r = wrp + it * 8;
                float4 v = __ldg((const float4*)(g_fused +
                                ((size_t)b * EE + cb + r) * HWN + tileTok) + c8);
                float a = s_attn[cb + r];
                uint16_t h0 = f16_hi(v.x * a), h1 = f16_hi(v.y * a);
                uint16_t h2 = f16_hi(v.z * a), h3 = f16_hi(v.w * a);
                uint2 hh = make_uint2((uint32_t)h0 | ((uint32_t)h1 << 16),
                                      (uint32_t)h2 | ((uint32_t)h3 << 16));
                *(uint2*)((char*)Ah + r * AROW + c8 * 8) = hh;
            }
        }
    };

    stage(0);
    CP_COMMIT();

    for (int q = 0; q < Q; ++q) {
        if (q + 1 < Q) {
            stage(q + 1);
            CP_COMMIT();
            CP_WAIT1();
        } else {
            CP_WAIT0();
        }
        __syncthreads();

        const uint32_t base = sb0 + (uint32_t)(q & 1) * STAGE;
        const uint32_t sAh = base, sWh = base + WOFF;
        #pragma unroll
        for (int k16 = 0; k16 < 4; ++k16) {
            const uint32_t kb = k16 * 16;
            uint32_t ahf[2][4];
            #pragma unroll
            for (int mi = 0; mi < 2; ++mi) {
                uint32_t ao = (kb + aRow0) * AROW + (aCol0 + mi * 16) * 2;
                LDSM_X4T(ahf[mi][0], ahf[mi][1], ahf[mi][2], ahf[mi][3], sAh + ao);
            }
            #pragma unroll
            for (int nh = 0; nh < 4; ++nh) {
                uint32_t wo = (wRow0 + nh * 16) * WROW + (kb + wKoff) * 2;
                uint32_t whf[4];
                LDSM_X4(whf[0], whf[1], whf[2], whf[3], sWh + wo);
                #pragma unroll
                for (int mi = 0; mi < 2; ++mi) {
                    mma_f16(acc[mi][nh * 2],     ahf[mi], whf[0], whf[1]);
                    mma_f16(acc[mi][nh * 2 + 1], ahf[mi], whf[2], whf[3]);
                }
            }
        }
        __syncthreads();   // buffer q&1 free for stage(q+2)
    }

    // ---- epilogue (proven) ----
    const int r0 = wm * 32 + (lane >> 2);
    if (TAPS > 0) {
        #pragma unroll
        for (int ni = 0; ni < 8; ++ni) {
            int ch = wn * 64 + ni * 8 + (lane & 3) * 2;
            float bv0 = __ldg(bias + ch), bv1 = __ldg(bias + ch + 1);
            float* d0 = g_fused + ((size_t)b * EE + c0 + ch) * HWN + tileTok;
            float* d1 = d0 + HWN;
            #pragma unroll
            for (int mi = 0; mi < 2; ++mi) {
                int m = r0 + mi * 16;
                d0[m]     = acc[mi][ni][0] + bv0;
                d1[m]     = acc[mi][ni][1] + bv1;
                d0[m + 8] = acc[mi][ni][2] + bv0;
                d1[m + 8] = acc[mi][ni][3] + bv1;
            }
        }
    } else {
        #pragma unroll
        for (int ni = 0; ni < 8; ++ni) {
            int chl = wn * 64 + ni * 8 + (lane & 3) * 2;
            int e = nb * 128 + chl;
            float bv0 = __ldg(bias + e), bv1 = __ldg(bias + e + 1);
            #pragma unroll
            for (int mi = 0; mi < 2; ++mi) {
                int m = r0 + mi * 16;
                float* da = out + ((size_t)b * HWN + tileTok + m) * EE + e;
                float* db = out + ((size_t)b * HWN + tileTok + m + 8) * EE + e;
                *(float2*)da = make_float2(acc[mi][ni][0] + bv0, acc[mi][ni][1] + bv1);
                *(float2*)db = make_float2(acc[mi][ni][2] + bv0, acc[mi][ni][3] + bv1);
            }
        }
    }
}

// ---------------- pool / attention / layernorm (unchanged, passing) ------
__global__ void pool_kernel() {
    int row = blockIdx.x;
    const float* p = g_fused + (size_t)row * HWN;
    int tid = threadIdx.x;
    float s = 0.f, m = -INFINITY;
    for (int i = tid; i < HWN; i += 256) { float v = p[i]; s += v; m = fmaxf(m, v); }
    __shared__ float ss[256], sm[256];
    ss[tid] = s; sm[tid] = m;
    __syncthreads();
    for (int st = 128; st > 0; st >>= 1) {
        if (tid < st) { ss[tid] += ss[tid + st]; sm[tid] = fmaxf(sm[tid], sm[tid + st]); }
        __syncthreads();
    }
    if (tid == 0) { g_avg[row] = ss[0] * (1.f / HWN); g_max[row] = sm[0]; }
}

__global__ void attn_kernel(const float* __restrict__ cw1, const float* __restrict__ cw2) {
    __shared__ float h1[24], h2[24];
    int b = blockIdx.x;
    int tid = threadIdx.x;
    if (tid < 24) {
        float s = 0.f;
        const float* w = cw1 + tid * EE;
        const float* v = g_avg + b * EE;
        #pragma unroll 4
        for (int c = 0; c < EE; ++c) s += v[c] * w[c];
        h1[tid] = fmaxf(s, 0.f);
    } else if (tid < 48) {
        int j = tid - 24;
        float s = 0.f;
        const float* w = cw1 + j * EE;
        const float* v = g_max + b * EE;
        #pragma unroll 4
        for (int c = 0; c < EE; ++c) s += v[c] * w[c];
        h2[j] = fmaxf(s, 0.f);
    }
    __syncthreads();
    float s = 0.f;
    const float* w = cw2 + tid * 24;
    #pragma unroll
    for (int j = 0; j < 24; ++j) s += (h1[j] + h2[j]) * w[j];
    g_attn[b * EE + tid] = 1.f / (1.f + expf(-s));
}

__global__ void ln_kernel(float* __restrict__ out, const float* __restrict__ g,
                          const float* __restrict__ beta) {
    int tokrow = blockIdx.x;
    float* p = out + (size_t)tokrow * EE;
    int tid = threadIdx.x;
    float v0 = p[tid], v1 = p[tid + 128], v2 = p[tid + 256];
    float s = v0 + v1 + v2;
    float q = v0 * v0 + v1 * v1 + v2 * v2;
    #pragma unroll
    for (int off = 16; off > 0; off >>= 1) {
        s += __shfl_down_sync(0xffffffffu, s, off);
        q += __shfl_down_sync(0xffffffffu, q, off);
    }
    __shared__ float rs[4], rq[4];
    __shared__ float smean, srstd;
    int wid = tid >> 5, lane = tid & 31;
    if (lane == 0) { rs[wid] = s; rq[wid] = q; }
    __syncthreads();
    if (tid == 0) {
        float ts = rs[0] + rs[1] + rs[2] + rs[3];
        float tq = rq[0] + rq[1] + rq[2] + rq[3];
        float mean = ts * (1.f / EE);
        float var  = tq * (1.f / EE) - mean * mean;
        smean = mean;
        srstd = rsqrtf(var + 1e-5f);
    }
    __syncthreads();
    float mean = smean, rstd = srstd;
    p[tid]       = (v0 - mean) * rstd * g[tid]       + beta[tid];
    p[tid + 128] = (v1 - mean) * rstd * g[tid + 128] + beta[tid + 128];
    p[tid + 256] = (v2 - mean) * rstd * g[tid + 256] + beta[tid + 256];
}

// ---------------- launch ---------------------------------------------------
extern "C" void kernel_launch(void* const* d_in, const int* in_sizes, int n_in,
                              void* d_out, int out_size) {
    const float* x   = (const float*)d_in[0];
    const float* w3  = (const float*)d_in[1];
    const float* b3  = (const float*)d_in[2];
    const float* w5  = (const float*)d_in[3];
    const float* b5  = (const float*)d_in[4];
    const float* w7  = (const float*)d_in[5];
    const float* b7  = (const float*)d_in[6];
    const float* cw1 = (const float*)d_in[7];
    const float* cw2 = (const float*)d_in[8];
    const float* fw  = (const float*)d_in[9];
    const float* fb  = (const float*)d_in[10];
    const float* lng = (const float*)d_in[11];
    const float* lnb = (const float*)d_in[12];
    float* out = (float*)d_out;

    cudaFuncSetAttribute(mm_kernel<3>, cudaFuncAttributeMaxDynamicSharedMemorySize, SMEM_SZ);
    cudaFuncSetAttribute(mm_kernel<5>, cudaFuncAttributeMaxDynamicSharedMemorySize, SMEM_SZ);
    cudaFuncSetAttribute(mm_kernel<7>, cudaFuncAttributeMaxDynamicSharedMemorySize, SMEM_SZ);
    cudaFuncSetAttribute(mm_kernel<0>, cudaFuncAttributeMaxDynamicSharedMemorySize, SMEM_SZ);

    prep_x<<<(int)((4ull * NPL + 255) / 256), 256>>>(x);
    prep_wc<3><<<(9  * 16384 + 255) / 256, 256>>>(w3);
    prep_wc<5><<<(25 * 16384 + 255) / 256, 256>>>(w5);
    prep_wc<7><<<(49 * 16384 + 255) / 256, 256>>>(w7);
    prep_wf<<<(EE * EE + 255) / 256, 256>>>(fw);

    dim3 cgrid(HWN / 128, BATCH);
    mm_kernel<3><<<cgrid, 256, SMEM_SZ>>>(b3, nullptr, 0);
    mm_kernel<5><<<cgrid, 256, SMEM_SZ>>>(b5, nullptr, EB);
    mm_kernel<7><<<cgrid, 256, SMEM_SZ>>>(b7, nullptr, 2 * EB);

    pool_kernel<<<BATCH * EE, 256>>>();
    attn_kernel<<<BATCH, EE>>>(cw1, cw2);

    dim3 ggrid(HWN / 128, BATCH, 3);
    mm_kernel<0><<<ggrid, 256, SMEM_SZ>>>(fb, out, 0);

    ln_kernel<<<BATCH * HWN, 128>>>(out, lng, lnb);
}